// round 14
// baseline (speedup 1.0000x reference)
#include <cuda_runtime.h>
#include <cuda_bf16.h>
#include <mma.h>
#include <math.h>
#include <cstdint>

using namespace nvcuda;
typedef __nv_bfloat16 bf16;
typedef __nv_bfloat162 bf162;
typedef unsigned int u32;

#define NN 50000
#define EE 800000
#define DD 128
#define HH 8

// ---------------- scratch ----------------
__device__ float g_Q[(size_t)NN * DD];
__device__ float g_K[(size_t)NN * DD];
__device__ float g_V[(size_t)NN * DD];
__device__ float g_wV[(size_t)NN * DD];
__device__ float g_z[(size_t)NN * HH];
__device__ float g_hmid[(size_t)NN * DD];
__device__ float g_emid[(size_t)EE * DD];
__device__ bf16  g_wB[229376];  // bf16 weights, natural [K,N]

#define OT_WQ   0
#define OT_WK   16384
#define OT_WV   32768
#define OT_WON  49152
#define OT_WOE  65536
#define OT_WE   81920
#define OT_W1N  98304
#define OT_W2N  131072
#define OT_W1E  163840
#define OT_W2E  196608

#define TSA 136                         // bf16 stride for A tile
#define AS_BYTES (128 * TSA * 2)        // 34816
#define AS64_BYTES (64 * TSA * 2)       // 17408
#define DW_FLOATS (16 * 68)             // per-warp fp32 dump (qkv kernel)
#define SMEM_G (AS_BYTES + 4 * DW_FLOATS * 4)     // 52224

#define PSTR 132
#define PBYTES (128 * PSTR * 4)         // 67584
#define P64BYTES (64 * PSTR * 4)        // 33792
#define HSTR 264                        // bf16 hid stride
#define H64BYTES (64 * HSTR * 2)        // 33792
#define DWS_FLOATS (16 * 20)            // per-warp small dump

#define SMEM_A64 (AS64_BYTES + P64BYTES)               // attnA64: 51200 (4 blocks/SM)
#define SMEM_M64 (AS64_BYTES + H64BYTES + 4 * DWS_FLOATS * 4)  // mlpE64: 56320 (4 blocks/SM)
#define OFF_DW  (AS_BYTES + PBYTES)
#define OFF_MV  (OFF_DW + 4 * DWS_FLOATS * 4)
#define SMEM_N  (OFF_MV + 128 * 8)                     // nodeN: 108544

typedef wmma::fragment<wmma::matrix_a, 16, 16, 16, bf16, wmma::row_major> FA;
typedef wmma::fragment<wmma::matrix_b, 16, 16, 16, bf16, wmma::row_major> FB;
typedef wmma::fragment<wmma::accumulator, 16, 16, 16, float> FC;

__device__ __forceinline__ void st_bf4(bf16* p, float4 v) {
    *(bf162*)(p)     = __floats2bfloat162_rn(v.x, v.y);
    *(bf162*)(p + 2) = __floats2bfloat162_rn(v.z, v.w);
}
__device__ __forceinline__ void red4(float* p, float4 v) {
    asm volatile("red.global.add.v4.f32 [%0], {%1,%2,%3,%4};"
                 :: "l"(p), "f"(v.x), "f"(v.y), "f"(v.z), "f"(v.w) : "memory");
}

// ---- staging: 128 rows, 4 warps ----
__device__ __forceinline__ void stage_ln(const float* __restrict__ A,
                                         const float* __restrict__ lnw,
                                         const float* __restrict__ lnb,
                                         bf16* As, int rowBase, int M, int w, int lane)
{
    float4 w4 = ((const float4*)lnw)[lane];
    float4 b4 = ((const float4*)lnb)[lane];
#pragma unroll
    for (int rr = 0; rr < 32; rr++) {
        int r = w * 32 + rr;
        int row = rowBase + r;
        float4 v = make_float4(0.f, 0.f, 0.f, 0.f);
        if (row < M) {
            v = *(const float4*)(A + (size_t)row * 128 + lane * 4);
            float s = v.x + v.y + v.z + v.w;
            float ss = v.x * v.x + v.y * v.y + v.z * v.z + v.w * v.w;
#pragma unroll
            for (int o = 16; o > 0; o >>= 1) {
                s += __shfl_xor_sync(0xffffffffu, s, o);
                ss += __shfl_xor_sync(0xffffffffu, ss, o);
            }
            float m = s * (1.f / 128.f);
            float var = ss * (1.f / 128.f) - m * m;
            float rs = rsqrtf(var + 1e-5f);
            v.x = (v.x - m) * rs * w4.x + b4.x;
            v.y = (v.y - m) * rs * w4.y + b4.y;
            v.z = (v.z - m) * rs * w4.z + b4.z;
            v.w = (v.w - m) * rs * w4.w + b4.w;
        }
        st_bf4(As + r * TSA + lane * 4, v);
    }
}

// ---- staging: 64 rows, 4 warps (16 rows each) ----
__device__ __forceinline__ void stage_ln64(const float* __restrict__ A,
                                           const float* __restrict__ lnw,
                                           const float* __restrict__ lnb,
                                           bf16* As, int rowBase, int M, int w, int lane)
{
    float4 w4 = ((const float4*)lnw)[lane];
    float4 b4 = ((const float4*)lnb)[lane];
#pragma unroll
    for (int rr = 0; rr < 16; rr++) {
        int r = w * 16 + rr;
        int row = rowBase + r;
        float4 v = make_float4(0.f, 0.f, 0.f, 0.f);
        if (row < M) {
            v = *(const float4*)(A + (size_t)row * 128 + lane * 4);
            float s = v.x + v.y + v.z + v.w;
            float ss = v.x * v.x + v.y * v.y + v.z * v.z + v.w * v.w;
#pragma unroll
            for (int o = 16; o > 0; o >>= 1) {
                s += __shfl_xor_sync(0xffffffffu, s, o);
                ss += __shfl_xor_sync(0xffffffffu, ss, o);
            }
            float m = s * (1.f / 128.f);
            float var = ss * (1.f / 128.f) - m * m;
            float rs = rsqrtf(var + 1e-5f);
            v.x = (v.x - m) * rs * w4.x + b4.x;
            v.y = (v.y - m) * rs * w4.y + b4.y;
            v.z = (v.z - m) * rs * w4.z + b4.z;
            v.w = (v.w - m) * rs * w4.w + b4.w;
        }
        st_bf4(As + r * TSA + lane * 4, v);
    }
}

// staging with wV/z division
__device__ __forceinline__ void stage_div(const float* __restrict__ wV,
                                          const float* __restrict__ z,
                                          bf16* As, int rowBase, int M, int tid)
{
#pragma unroll
    for (int it = 0; it < 32; it++) {
        int f = tid + it * 128;
        int r = f >> 5;
        int c = (f & 31) << 2;
        int row = rowBase + r;
        float4 v = make_float4(0.f, 0.f, 0.f, 0.f);
        if (row < M) {
            v = *(const float4*)(wV + (size_t)row * 128 + c);
            float inv = 1.f / (z[(size_t)row * 8 + (c >> 4)] + 1e-8f);
            v.x *= inv; v.y *= inv; v.z *= inv; v.w *= inv;
        }
        st_bf4(As + r * TSA + c, v);
    }
}

// one K=128 chunk; warp tile 64x64 (4 warps: wm=w>>1, wn=w&1)
__device__ __forceinline__ void mma_loopS(const bf16* As, int lda, const bf16* __restrict__ Bg,
                                          int ldB, int wm, FC acc[4][4])
{
#pragma unroll
    for (int kk = 0; kk < 128; kk += 16) {
        FA fa[4];
        FB fb[4];
#pragma unroll
        for (int i = 0; i < 4; i++)
            wmma::load_matrix_sync(fa[i], As + (size_t)(wm * 64 + i * 16) * lda + kk, lda);
#pragma unroll
        for (int j = 0; j < 4; j++)
            wmma::load_matrix_sync(fb[j], Bg + (size_t)kk * ldB + j * 16, ldB);
#pragma unroll
        for (int i = 0; i < 4; i++)
#pragma unroll
            for (int j = 0; j < 4; j++)
                wmma::mma_sync(acc[i][j], fa[i], fb[j], acc[i][j]);
    }
}

// K=128 chunk; warp covers 64 rows x 32 cols
__device__ __forceinline__ void mma32h(const bf16* As64, int lda, const bf16* __restrict__ Bg,
                                       int ldB, FC acc[4][2])
{
#pragma unroll
    for (int kk = 0; kk < 128; kk += 16) {
        FA fa[4];
        FB fb[2];
#pragma unroll
        for (int i = 0; i < 4; i++)
            wmma::load_matrix_sync(fa[i], As64 + (size_t)(i * 16) * lda + kk, lda);
#pragma unroll
        for (int j = 0; j < 2; j++)
            wmma::load_matrix_sync(fb[j], Bg + (size_t)kk * ldB + j * 16, ldB);
#pragma unroll
        for (int i = 0; i < 4; i++)
#pragma unroll
            for (int j = 0; j < 2; j++)
                wmma::mma_sync(acc[i][j], fa[i], fb[j], acc[i][j]);
    }
}

__device__ __forceinline__ void zero_acc(FC acc[4][4]) {
#pragma unroll
    for (int i = 0; i < 4; i++)
#pragma unroll
        for (int j = 0; j < 4; j++) wmma::fill_fragment(acc[i][j], 0.f);
}
__device__ __forceinline__ void zero2(FC acc[4][2]) {
#pragma unroll
    for (int i = 0; i < 4; i++)
#pragma unroll
        for (int j = 0; j < 2; j++) wmma::fill_fragment(acc[i][j], 0.f);
}

__device__ __forceinline__ void dump_P(float* P, FC acc[4][4], int wm, int wn) {
#pragma unroll
    for (int i = 0; i < 4; i++)
#pragma unroll
        for (int j = 0; j < 4; j++)
            wmma::store_matrix_sync(P + (wm * 64 + i * 16) * PSTR + wn * 64 + j * 16,
                                    acc[i][j], PSTR, wmma::mem_row_major);
}

// dump 64x32 warp result into 64x132 P
__device__ __forceinline__ void dump32(float* P, FC acc[4][2], int w) {
#pragma unroll
    for (int i = 0; i < 4; i++)
#pragma unroll
        for (int j = 0; j < 2; j++)
            wmma::store_matrix_sync(P + (i * 16) * PSTR + w * 32 + j * 16,
                                    acc[i][j], PSTR, wmma::mem_row_major);
}

// shared: w1 (+SiLU) into hid region, via per-warp Dw (128-row kernels)
__device__ __forceinline__ void w1_to_hid(const bf16* As, bf16* hid, float* Dw,
                                          const bf16* __restrict__ W1T,
                                          int wm, int wn, int lane, FC acc[4][4])
{
    const int rloc = lane >> 1;
    const int h8 = (lane & 1) * 8;
#pragma unroll
    for (int t = 0; t < 2; t++) {
        zero_acc(acc);
        mma_loopS(As, TSA, W1T + t * 128 + wn * 64, 256, wm, acc);
#pragma unroll
        for (int i = 0; i < 4; i++) {
#pragma unroll
            for (int j = 0; j < 4; j++) {
                wmma::store_matrix_sync(Dw, acc[i][j], 20, wmma::mem_row_major);
                __syncwarp();
                int r = wm * 64 + i * 16 + rloc;
                int c = t * 128 + wn * 64 + j * 16 + h8;
#pragma unroll
                for (int c4 = 0; c4 < 2; c4++) {
                    float4 v = *(const float4*)(Dw + rloc * 20 + h8 + c4 * 4);
                    v.x = v.x / (1.f + __expf(-v.x));
                    v.y = v.y / (1.f + __expf(-v.y));
                    v.z = v.z / (1.f + __expf(-v.z));
                    v.w = v.w / (1.f + __expf(-v.w));
                    st_bf4(hid + (size_t)r * HSTR + c + c4 * 4, v);
                }
                __syncwarp();
            }
        }
    }
}

// shared: w2 + residual(from gmem fp32) -> out (128-row kernels)
__device__ __forceinline__ void w2_out(const bf16* hid, float* Dw,
                                       const bf16* __restrict__ W2T,
                                       const float* __restrict__ Rin, float* __restrict__ out,
                                       int rowBase, int M, int wm, int wn, int lane, FC acc[4][4])
{
    const int rloc = lane >> 1;
    const int h8 = (lane & 1) * 8;
    zero_acc(acc);
#pragma unroll
    for (int ch = 0; ch < 2; ch++)
        mma_loopS(hid + ch * 128, HSTR, W2T + (size_t)(ch * 128) * 128 + wn * 64, 128, wm, acc);
    __syncthreads();
#pragma unroll
    for (int i = 0; i < 4; i++) {
#pragma unroll
        for (int j = 0; j < 4; j++) {
            wmma::store_matrix_sync(Dw, acc[i][j], 20, wmma::mem_row_major);
            __syncwarp();
            int row = rowBase + wm * 64 + i * 16 + rloc;
            int c = wn * 64 + j * 16 + h8;
            if (row < M) {
#pragma unroll
                for (int c4 = 0; c4 < 2; c4++) {
                    float4 v = *(const float4*)(Dw + rloc * 20 + h8 + c4 * 4);
                    float4 rv = *(const float4*)(Rin + (size_t)row * 128 + c + c4 * 4);
                    v.x += rv.x; v.y += rv.y; v.z += rv.z; v.w += rv.w;
                    *(float4*)(out + (size_t)row * 128 + c + c4 * 4) = v;
                }
            }
            __syncwarp();
        }
    }
}

// per-warp epilogue through a 16x68 fp32 dump region (qkv)
__device__ __forceinline__ void epi_bias(float* Dw, FC acc[4][4],
                                         int wm, int wn, int lane, int rowBase,
                                         const float* bias, float* C, int M)
{
    const int rloc = lane >> 1;
    const int half = lane & 1;
#pragma unroll
    for (int i = 0; i < 4; i++) {
#pragma unroll
        for (int j = 0; j < 4; j++)
            wmma::store_matrix_sync(Dw + j * 16, acc[i][j], 68, wmma::mem_row_major);
        __syncwarp();
        int row = rowBase + wm * 64 + i * 16 + rloc;
        if (row < M) {
#pragma unroll
            for (int c4 = 0; c4 < 8; c4++) {
                int c = half * 32 + c4 * 4;
                float4 v = *(const float4*)(Dw + rloc * 68 + c);
                int gc = wn * 64 + c;
                float4 bv = *(const float4*)(bias + gc);
                v.x += bv.x; v.y += bv.y; v.z += bv.z; v.w += bv.w;
                *(float4*)(C + (size_t)row * 128 + gc) = v;
            }
        }
        __syncwarp();
    }
}

// ---------------- QKV fused ----------------
__global__ void __launch_bounds__(128) qkv14(
    const float* __restrict__ nf, const bf16* __restrict__ wT,
    const float* __restrict__ bq, const float* __restrict__ bk, const float* __restrict__ bv,
    const float* __restrict__ lnw, const float* __restrict__ lnb,
    float* __restrict__ Q, float* __restrict__ K, float* __restrict__ V)
{
    extern __shared__ char smraw[];
    bf16* As = (bf16*)smraw;
    float* Ds = (float*)(smraw + AS_BYTES);
    const int tid = threadIdx.x;
    const int w = tid >> 5, lane = tid & 31;
    const int wm = w >> 1, wn = w & 1;
    const int rowBase = blockIdx.x * 128;

    stage_ln(nf, lnw, lnb, As, rowBase, NN, w, lane);
    __syncthreads();

    const bf16* Wts[3] = {wT + OT_WQ, wT + OT_WK, wT + OT_WV};
    const float* bs[3] = {bq, bk, bv};
    float* outs[3] = {Q, K, V};

#pragma unroll
    for (int t = 0; t < 3; t++) {
        FC acc[4][4];
        zero_acc(acc);
        mma_loopS(As, TSA, Wts[t] + wn * 64, 128, wm, acc);
        epi_bias(Ds + w * DW_FLOATS, acc, wm, wn, lane, rowBase, bs[t], outs[t], NN);
    }
}

// ---------------- attnA64: 64-edge blocks, 4 blocks/SM ----------------
__global__ void __launch_bounds__(128, 4) attnA64(
    const float* __restrict__ ef,
    const bf16* __restrict__ WeT, const bf16* __restrict__ WoeT,
    const float* __restrict__ ln1w, const float* __restrict__ ln1b,
    const float* __restrict__ be, const float* __restrict__ boe,
    const float* __restrict__ Qm, const float* __restrict__ Km, const float* __restrict__ Vm,
    const int* __restrict__ src, const int* __restrict__ dst,
    float* __restrict__ emid, float* __restrict__ wV, float* __restrict__ z)
{
    extern __shared__ char smraw[];
    bf16* As = (bf16*)smraw;                     // 64 x TSA bf16
    float* P = (float*)(smraw + AS64_BYTES);     // 64 x 132 fp32
    const int tid = threadIdx.x;
    const int w = tid >> 5, lane = tid & 31;
    const int rowBase = blockIdx.x * 64;

    // 1) proj = LN1e(ef) @ We -> P
    stage_ln64(ef, ln1w, ln1b, As, rowBase, EE, w, lane);
    __syncthreads();

    FC acc[4][2];
    zero2(acc);
    mma32h(As, TSA, WeT + w * 32, 128, acc);
    __syncthreads();
    dump32(P, acc, w);
    __syncthreads();

    // 2) scoring: 2 threads per edge, 4 heads each; eo -> As (bf16)
    {
        const int r = tid >> 1;
        const int h0 = (tid & 1) * 4;
        const size_t e = (size_t)rowBase + r;
        const int sN = src[e], dN = dst[e];
        const float* Kp = Km + (size_t)sN * 128;
        const float* Qp = Qm + (size_t)dN * 128;
        const float* Vp = Vm + (size_t)sN * 128;
        float* wd = wV + (size_t)dN * 128;
#pragma unroll
        for (int h = h0; h < h0 + 4; h++) {
            const int c0 = h * 16;
            float sum = 0.f;
            float4 eo[4];
#pragma unroll
            for (int q4 = 0; q4 < 4; q4++) {
                float4 p = *(const float4*)(P + r * PSTR + c0 + q4 * 4);
                float4 bv = *(const float4*)(be + c0 + q4 * 4);
                p.x += bv.x; p.y += bv.y; p.z += bv.z; p.w += bv.w;
                float4 kk = *(const float4*)(Kp + c0 + q4 * 4);
                float4 qq = *(const float4*)(Qp + c0 + q4 * 4);
                float s0 = fminf(5.f, fmaxf(-5.f, kk.x * qq.x * 0.25f));
                float s1 = fminf(5.f, fmaxf(-5.f, kk.y * qq.y * 0.25f));
                float s2 = fminf(5.f, fmaxf(-5.f, kk.z * qq.z * 0.25f));
                float s3 = fminf(5.f, fmaxf(-5.f, kk.w * qq.w * 0.25f));
                eo[q4] = make_float4(s0 * p.x, s1 * p.y, s2 * p.z, s3 * p.w);
                sum += eo[q4].x + eo[q4].y + eo[q4].z + eo[q4].w;
            }
#pragma unroll
            for (int q4 = 0; q4 < 4; q4++)
                st_bf4(As + r * TSA + c0 + q4 * 4, eo[q4]);
            float wgt = __expf(fminf(5.f, fmaxf(-5.f, sum)));
#pragma unroll
            for (int q4 = 0; q4 < 4; q4++) {
                float4 vv = *(const float4*)(Vp + c0 + q4 * 4);
                red4(wd + c0 + q4 * 4, make_float4(vv.x * wgt, vv.y * wgt, vv.z * wgt, vv.w * wgt));
            }
            atomicAdd(z + (size_t)dN * 8 + h, wgt);
        }
    }
    __syncthreads();

    // 3) emid = eo @ Wo_e + bo_e + ef
    zero2(acc);
    mma32h(As, TSA, WoeT + w * 32, 128, acc);
    __syncthreads();
    dump32(P, acc, w);
    __syncthreads();
    {
        const int r = tid >> 1;
        const int hsel = tid & 1;
        const size_t row = (size_t)rowBase + r;
#pragma unroll
        for (int c4 = 0; c4 < 16; c4++) {
            int c = hsel * 64 + c4 * 4;
            float4 v = *(const float4*)(P + r * PSTR + c);
            float4 bb = *(const float4*)(boe + c);
            float4 rv = *(const float4*)(ef + row * 128 + c);
            v.x += bb.x + rv.x; v.y += bb.y + rv.y; v.z += bb.z + rv.z; v.w += bb.w + rv.w;
            *(float4*)(emid + row * 128 + c) = v;
        }
    }
}

// ---------------- mlpE64: 64-row blocks, 4 blocks/SM ----------------
__global__ void __launch_bounds__(128, 4) mlpE64(
    const float* __restrict__ emid,
    const bf16* __restrict__ W1T, const bf16* __restrict__ W2T,
    const float* __restrict__ ln2w, const float* __restrict__ ln2b,
    float* __restrict__ oute)
{
    extern __shared__ char smraw[];
    bf16* As = (bf16*)smraw;                              // 64 x TSA bf16
    bf16* hid = (bf16*)(smraw + AS64_BYTES);              // 64 x HSTR bf16
    float* Dw = (float*)(smraw + AS64_BYTES + H64BYTES) + (threadIdx.x >> 5) * DWS_FLOATS;
    const int tid = threadIdx.x;
    const int w = tid >> 5, lane = tid & 31;
    const int rloc = lane >> 1;
    const int h8 = (lane & 1) * 8;
    const int rowBase = blockIdx.x * 64;

    stage_ln64(emid, ln2w, ln2b, As, rowBase, EE, w, lane);
    __syncthreads();

    // w1: C = 64 x 256 ; warp w covers cols [w*64, w*64+64)
    {
        FC acc[4][4];
        zero_acc(acc);
#pragma unroll
        for (int kk = 0; kk < 128; kk += 16) {
            FA fa[4];
            FB fb[4];
#pragma unroll
            for (int i = 0; i < 4; i++)
                wmma::load_matrix_sync(fa[i], As + (size_t)(i * 16) * TSA + kk, TSA);
#pragma unroll
            for (int j = 0; j < 4; j++)
                wmma::load_matrix_sync(fb[j], W1T + (size_t)kk * 256 + w * 64 + j * 16, 256);
#pragma unroll
            for (int i = 0; i < 4; i++)
#pragma unroll
                for (int j = 0; j < 4; j++)
                    wmma::mma_sync(acc[i][j], fa[i], fb[j], acc[i][j]);
        }
#pragma unroll
        for (int i = 0; i < 4; i++) {
#pragma unroll
            for (int j = 0; j < 4; j++) {
                wmma::store_matrix_sync(Dw, acc[i][j], 20, wmma::mem_row_major);
                __syncwarp();
                int r = i * 16 + rloc;
                int c = w * 64 + j * 16 + h8;
#pragma unroll
                for (int c4 = 0; c4 < 2; c4++) {
                    float4 v = *(const float4*)(Dw + rloc * 20 + h8 + c4 * 4);
                    v.x = v.x / (1.f + __expf(-v.x));
                    v.y = v.y / (1.f + __expf(-v.y));
                    v.z = v.z / (1.f + __expf(-v.z));
                    v.w = v.w / (1.f + __expf(-v.w));
                    st_bf4(hid + (size_t)r * HSTR + c + c4 * 4, v);
                }
                __syncwarp();
            }
        }
    }
    __syncthreads();

    // w2: C = 64 x 128, K=256 ; warp w covers cols [w*32, w*32+32)
    {
        FC acc[4][2];
        zero2(acc);
#pragma unroll
        for (int ch = 0; ch < 2; ch++)
            mma32h(hid + ch * 128, HSTR, W2T + (size_t)(ch * 128) * 128 + w * 32, 128, acc);
        __syncthreads();
#pragma unroll
        for (int i = 0; i < 4; i++) {
#pragma unroll
            for (int j = 0; j < 2; j++) {
                wmma::store_matrix_sync(Dw, acc[i][j], 20, wmma::mem_row_major);
                __syncwarp();
                size_t row = (size_t)rowBase + i * 16 + rloc;
                int c = w * 32 + j * 16 + h8;
#pragma unroll
                for (int c4 = 0; c4 < 2; c4++) {
                    float4 v = *(const float4*)(Dw + rloc * 20 + h8 + c4 * 4);
                    float4 rv = *(const float4*)(emid + row * 128 + c + c4 * 4);
                    v.x += rv.x; v.y += rv.y; v.z += rv.z; v.w += rv.w;
                    *(float4*)(oute + row * 128 + c + c4 * 4) = v;
                }
                __syncwarp();
            }
        }
    }
}

// ---------------- nodeN ----------------
__global__ void __launch_bounds__(128) nodeN(
    const float* __restrict__ wV, const float* __restrict__ z,
    const float* __restrict__ nf,
    const bf16* __restrict__ WonT, const bf16* __restrict__ W1T, const bf16* __restrict__ W2T,
    const float* __restrict__ bon,
    const float* __restrict__ ln2w, const float* __restrict__ ln2b,
    float* __restrict__ hmid, float* __restrict__ outh)
{
    extern __shared__ char smraw[];
    bf16* As = (bf16*)smraw;
    float* P = (float*)(smraw + AS_BYTES);
    bf16* hid = (bf16*)P;
    float* Dw = (float*)(smraw + OFF_DW) + (threadIdx.x >> 5) * DWS_FLOATS;
    float2* MV = (float2*)(smraw + OFF_MV);
    const int tid = threadIdx.x;
    const int w = tid >> 5, lane = tid & 31;
    const int wm = w >> 1, wn = w & 1;
    const int rowBase = blockIdx.x * 128;

    stage_div(wV, z, As, rowBase, NN, tid);
    __syncthreads();
    FC acc[4][4];
    zero_acc(acc);
    mma_loopS(As, TSA, WonT + wn * 64, 128, wm, acc);
    __syncthreads();
    dump_P(P, acc, wm, wn);
    __syncthreads();
    {
        const int r = tid;
        const int row = rowBase + r;
        if (row < NN) {
            float s = 0.f, ss = 0.f;
#pragma unroll
            for (int c4 = 0; c4 < 32; c4++) {
                int c = c4 * 4;
                float4 v = *(const float4*)(P + r * PSTR + c);
                float4 bb = *(const float4*)(bon + c);
                float4 rv = *(const float4*)(nf + (size_t)row * 128 + c);
                v.x += bb.x + rv.x; v.y += bb.y + rv.y; v.z += bb.z + rv.z; v.w += bb.w + rv.w;
                *(float4*)(P + r * PSTR + c) = v;
                *(float4*)(hmid + (size_t)row * 128 + c) = v;
                s += v.x + v.y + v.z + v.w;
                ss += v.x * v.x + v.y * v.y + v.z * v.z + v.w * v.w;
            }
            float m = s * (1.f / 128.f);
            float var = ss * (1.f / 128.f) - m * m;
            MV[r] = make_float2(m, rsqrtf(var + 1e-5f));
        } else {
            MV[r] = make_float2(0.f, 0.f);
        }
    }
    __syncthreads();

    {
        float4 w4 = ((const float4*)ln2w)[lane];
        float4 b4 = ((const float4*)ln2b)[lane];
#pragma unroll
        for (int rr = 0; rr < 32; rr++) {
            int r = w * 32 + rr;
            float2 mv = MV[r];
            float4 v = *(const float4*)(P + r * PSTR + lane * 4);
            v.x = (v.x - mv.x) * mv.y * w4.x + b4.x;
            v.y = (v.y - mv.x) * mv.y * w4.y + b4.y;
            v.z = (v.z - mv.x) * mv.y * w4.z + b4.z;
            v.w = (v.w - mv.x) * mv.y * w4.w + b4.w;
            st_bf4(As + r * TSA + lane * 4, v);
        }
    }
    __syncthreads();

    w1_to_hid(As, hid, Dw, W1T, wm, wn, lane, acc);
    __syncthreads();
    w2_out(hid, Dw, W2T, hmid, outh, rowBase, NN, wm, wn, lane, acc);
}

// ---------------- weight prep ----------------
struct WPrep {
    const float* in[10];
    bf16* out[10];
    int n[10];
};
__global__ void wprep_all(WPrep wp)
{
    int t = blockIdx.y;
    int count = wp.n[t];
    const float* in = wp.in[t];
    bf16* out = wp.out[t];
    for (int idx = blockIdx.x * 256 + threadIdx.x; idx < count; idx += gridDim.x * 256)
        out[idx] = __float2bfloat16_rn(in[idx]);
}

// ---------------- launch ----------------
extern "C" void kernel_launch(void* const* d_in, const int* in_sizes, int n_in,
                              void* d_out, int out_size)
{
    const float* node_feats = (const float*)d_in[0];
    const float* edge_feats = (const float*)d_in[1];
    const int*   src        = (const int*)d_in[2];
    const int*   dst        = (const int*)d_in[3];
    const float* ln1n_w = (const float*)d_in[4];
    const float* ln1n_b = (const float*)d_in[5];
    const float* ln1e_w = (const float*)d_in[6];
    const float* ln1e_b = (const float*)d_in[7];
    const float* ln2n_w = (const float*)d_in[8];
    const float* ln2n_b = (const float*)d_in[9];
    const float* ln2e_w = (const float*)d_in[10];
    const float* ln2e_b = (const float*)d_in[11];
    const float* Wq = (const float*)d_in[12];
    const float* bq = (const float*)d_in[13];
    const float* Wk = (const float*)d_in[14];
    const float* bk = (const float*)d_in[15];
    const float* Wv = (const float*)d_in[16];
    const float* bv = (const float*)d_in[17];
    const float* We = (const float*)d_in[18];
    const float* be = (const float*)d_in[19];
    const float* Wo_n = (const float*)d_in[20];
    const float* bo_n = (const float*)d_in[21];
    const float* Wo_e = (const float*)d_in[22];
    const float* bo_e = (const float*)d_in[23];
    const float* mlp_n_w1 = (const float*)d_in[24];
    const float* mlp_n_w2 = (const float*)d_in[25];
    const float* mlp_e_w1 = (const float*)d_in[26];
    const float* mlp_e_w2 = (const float*)d_in[27];

    float* outh = (float*)d_out;
    float* oute = outh + (size_t)NN * DD;

    float *p_Q, *p_K, *p_V, *p_wV, *p_z, *p_hmid, *p_emid;
    bf16 *p_wB;
    cudaGetSymbolAddress((void**)&p_Q, g_Q);
    cudaGetSymbolAddress((void**)&p_K, g_K);
    cudaGetSymbolAddress((void**)&p_V, g_V);
    cudaGetSymbolAddress((void**)&p_wV, g_wV);
    cudaGetSymbolAddress((void**)&p_z, g_z);
    cudaGetSymbolAddress((void**)&p_hmid, g_hmid);
    cudaGetSymbolAddress((void**)&p_emid, g_emid);
    cudaGetSymbolAddress((void**)&p_wB, g_wB);

    static cudaStream_t sA = nullptr;
    static cudaEvent_t evF = nullptr, evJ = nullptr;
    if (!sA) {
        cudaStreamCreateWithFlags(&sA, cudaStreamNonBlocking);
        cudaEventCreateWithFlags(&evF, cudaEventDisableTiming);
        cudaEventCreateWithFlags(&evJ, cudaEventDisableTiming);
    }

    cudaFuncSetAttribute(qkv14, cudaFuncAttributeMaxDynamicSharedMemorySize, SMEM_G);
    cudaFuncSetAttribute(attnA64, cudaFuncAttributeMaxDynamicSharedMemorySize, SMEM_A64);
    cudaFuncSetAttribute(mlpE64, cudaFuncAttributeMaxDynamicSharedMemorySize, SMEM_M64);
    cudaFuncSetAttribute(nodeN, cudaFuncAttributeMaxDynamicSharedMemorySize, SMEM_N);

    cudaMemsetAsync(p_wV, 0, (size_t)NN * DD * sizeof(float));
    cudaMemsetAsync(p_z, 0, (size_t)NN * HH * sizeof(float));

    WPrep wp;
    wp.in[0] = Wq;       wp.out[0] = p_wB + OT_WQ;  wp.n[0] = 16384;
    wp.in[1] = Wk;       wp.out[1] = p_wB + OT_WK;  wp.n[1] = 16384;
    wp.in[2] = Wv;       wp.out[2] = p_wB + OT_WV;  wp.n[2] = 16384;
    wp.in[3] = Wo_n;     wp.out[3] = p_wB + OT_WON; wp.n[3] = 16384;
    wp.in[4] = Wo_e;     wp.out[4] = p_wB + OT_WOE; wp.n[4] = 16384;
    wp.in[5] = We;       wp.out[5] = p_wB + OT_WE;  wp.n[5] = 16384;
    wp.in[6] = mlp_n_w1; wp.out[6] = p_wB + OT_W1N; wp.n[6] = 32768;
    wp.in[7] = mlp_n_w2; wp.out[7] = p_wB + OT_W2N; wp.n[7] = 32768;
    wp.in[8] = mlp_e_w1; wp.out[8] = p_wB + OT_W1E; wp.n[8] = 32768;
    wp.in[9] = mlp_e_w2; wp.out[9] = p_wB + OT_W2E; wp.n[9] = 32768;
    wprep_all<<<dim3(32, 10), 256>>>(wp);

    const int gN = (NN + 127) / 128;   // 391
    const int gE64 = EE / 64;          // 12500

    qkv14<<<gN, 128, SMEM_G>>>(node_feats, p_wB, bq, bk, bv, ln1n_w, ln1n_b, p_Q, p_K, p_V);

    attnA64<<<gE64, 128, SMEM_A64>>>(edge_feats, p_wB + OT_WE, p_wB + OT_WOE,
                                     ln1e_w, ln1e_b, be, bo_e,
                                     p_Q, p_K, p_V, src, dst,
                                     p_emid, p_wV, p_z);

    // fork: edge MLP on side stream, node chain on main stream
    cudaEventRecord(evF, 0);
    cudaStreamWaitEvent(sA, evF, 0);

    mlpE64<<<gE64, 128, SMEM_M64, sA>>>(p_emid, p_wB + OT_W1E, p_wB + OT_W2E,
                                        ln2e_w, ln2e_b, oute);

    nodeN<<<gN, 128, SMEM_N>>>(p_wV, p_z, node_feats,
                               p_wB + OT_WON, p_wB + OT_W1N, p_wB + OT_W2N,
                               bo_n, ln2n_w, ln2n_b, p_hmid, outh);

    // join
    cudaEventRecord(evJ, sA);
    cudaStreamWaitEvent(0, evJ, 0);
}

// round 15
// speedup vs baseline: 1.0264x; 1.0264x over previous
#include <cuda_runtime.h>
#include <cuda_bf16.h>
#include <mma.h>
#include <math.h>
#include <cstdint>

using namespace nvcuda;
typedef __nv_bfloat16 bf16;
typedef __nv_bfloat162 bf162;
typedef unsigned int u32;

#define NN 50000
#define EE 800000
#define DD 128
#define HH 8

// ---------------- scratch ----------------
__device__ float g_Q[(size_t)NN * DD];
__device__ float g_K[(size_t)NN * DD];
__device__ float g_V[(size_t)NN * DD];
__device__ float g_wV[(size_t)NN * DD];
__device__ float g_z[(size_t)NN * HH];
__device__ float g_hmid[(size_t)NN * DD];
__device__ float g_emid[(size_t)EE * DD];
__device__ bf16  g_wB[229376];  // bf16 weights, natural [K,N]

#define OT_WQ   0
#define OT_WK   16384
#define OT_WV   32768
#define OT_WON  49152
#define OT_WOE  65536
#define OT_WE   81920
#define OT_W1N  98304
#define OT_W2N  131072
#define OT_W1E  163840
#define OT_W2E  196608

#define TSA 136                         // bf16 stride for A tile
#define AS_BYTES (128 * TSA * 2)        // 34816
#define AS64_BYTES (64 * TSA * 2)       // 17408
#define DW_FLOATS (16 * 68)             // per-warp fp32 dump (qkv kernel)
#define SMEM_G (AS_BYTES + 4 * DW_FLOATS * 4)     // 52224

#define PSTR 132
#define PBYTES (128 * PSTR * 4)         // 67584
#define P64BYTES (64 * PSTR * 4)        // 33792
#define HSTR 264                        // bf16 hid stride
#define H64BYTES (64 * HSTR * 2)        // 33792
#define DWS_FLOATS (16 * 20)            // per-warp small dump

#define SMEM_A64 (AS64_BYTES + P64BYTES)               // attnA64: 51200 (4 blocks/SM)
#define SMEM_M64 (AS64_BYTES + H64BYTES + 4 * DWS_FLOATS * 4)  // mlpE64: 56320 (3 blocks/SM)
#define OFF_DW  (AS_BYTES + PBYTES)
#define OFF_MV  (OFF_DW + 4 * DWS_FLOATS * 4)
#define SMEM_N  (OFF_MV + 128 * 8)                     // nodeN: 108544

typedef wmma::fragment<wmma::matrix_a, 16, 16, 16, bf16, wmma::row_major> FA;
typedef wmma::fragment<wmma::matrix_b, 16, 16, 16, bf16, wmma::row_major> FB;
typedef wmma::fragment<wmma::accumulator, 16, 16, 16, float> FC;

__device__ __forceinline__ void st_bf4(bf16* p, float4 v) {
    *(bf162*)(p)     = __floats2bfloat162_rn(v.x, v.y);
    *(bf162*)(p + 2) = __floats2bfloat162_rn(v.z, v.w);
}
__device__ __forceinline__ void red4(float* p, float4 v) {
    asm volatile("red.global.add.v4.f32 [%0], {%1,%2,%3,%4};"
                 :: "l"(p), "f"(v.x), "f"(v.y), "f"(v.z), "f"(v.w) : "memory");
}

// ---- staging: 128 rows, 4 warps ----
__device__ __forceinline__ void stage_ln(const float* __restrict__ A,
                                         const float* __restrict__ lnw,
                                         const float* __restrict__ lnb,
                                         bf16* As, int rowBase, int M, int w, int lane)
{
    float4 w4 = ((const float4*)lnw)[lane];
    float4 b4 = ((const float4*)lnb)[lane];
#pragma unroll
    for (int rr = 0; rr < 32; rr++) {
        int r = w * 32 + rr;
        int row = rowBase + r;
        float4 v = make_float4(0.f, 0.f, 0.f, 0.f);
        if (row < M) {
            v = *(const float4*)(A + (size_t)row * 128 + lane * 4);
            float s = v.x + v.y + v.z + v.w;
            float ss = v.x * v.x + v.y * v.y + v.z * v.z + v.w * v.w;
#pragma unroll
            for (int o = 16; o > 0; o >>= 1) {
                s += __shfl_xor_sync(0xffffffffu, s, o);
                ss += __shfl_xor_sync(0xffffffffu, ss, o);
            }
            float m = s * (1.f / 128.f);
            float var = ss * (1.f / 128.f) - m * m;
            float rs = rsqrtf(var + 1e-5f);
            v.x = (v.x - m) * rs * w4.x + b4.x;
            v.y = (v.y - m) * rs * w4.y + b4.y;
            v.z = (v.z - m) * rs * w4.z + b4.z;
            v.w = (v.w - m) * rs * w4.w + b4.w;
        }
        st_bf4(As + r * TSA + lane * 4, v);
    }
}

// ---- staging: 64 rows, 4 warps (16 rows each) ----
__device__ __forceinline__ void stage_ln64(const float* __restrict__ A,
                                           const float* __restrict__ lnw,
                                           const float* __restrict__ lnb,
                                           bf16* As, int rowBase, int M, int w, int lane)
{
    float4 w4 = ((const float4*)lnw)[lane];
    float4 b4 = ((const float4*)lnb)[lane];
#pragma unroll
    for (int rr = 0; rr < 16; rr++) {
        int r = w * 16 + rr;
        int row = rowBase + r;
        float4 v = make_float4(0.f, 0.f, 0.f, 0.f);
        if (row < M) {
            v = *(const float4*)(A + (size_t)row * 128 + lane * 4);
            float s = v.x + v.y + v.z + v.w;
            float ss = v.x * v.x + v.y * v.y + v.z * v.z + v.w * v.w;
#pragma unroll
            for (int o = 16; o > 0; o >>= 1) {
                s += __shfl_xor_sync(0xffffffffu, s, o);
                ss += __shfl_xor_sync(0xffffffffu, ss, o);
            }
            float m = s * (1.f / 128.f);
            float var = ss * (1.f / 128.f) - m * m;
            float rs = rsqrtf(var + 1e-5f);
            v.x = (v.x - m) * rs * w4.x + b4.x;
            v.y = (v.y - m) * rs * w4.y + b4.y;
            v.z = (v.z - m) * rs * w4.z + b4.z;
            v.w = (v.w - m) * rs * w4.w + b4.w;
        }
        st_bf4(As + r * TSA + lane * 4, v);
    }
}

// staging with wV/z division
__device__ __forceinline__ void stage_div(const float* __restrict__ wV,
                                          const float* __restrict__ z,
                                          bf16* As, int rowBase, int M, int tid)
{
#pragma unroll
    for (int it = 0; it < 32; it++) {
        int f = tid + it * 128;
        int r = f >> 5;
        int c = (f & 31) << 2;
        int row = rowBase + r;
        float4 v = make_float4(0.f, 0.f, 0.f, 0.f);
        if (row < M) {
            v = *(const float4*)(wV + (size_t)row * 128 + c);
            float inv = 1.f / (z[(size_t)row * 8 + (c >> 4)] + 1e-8f);
            v.x *= inv; v.y *= inv; v.z *= inv; v.w *= inv;
        }
        st_bf4(As + r * TSA + c, v);
    }
}

// one K=128 chunk; warp tile 64x64 (4 warps: wm=w>>1, wn=w&1)
__device__ __forceinline__ void mma_loopS(const bf16* As, int lda, const bf16* __restrict__ Bg,
                                          int ldB, int wm, FC acc[4][4])
{
#pragma unroll
    for (int kk = 0; kk < 128; kk += 16) {
        FA fa[4];
        FB fb[4];
#pragma unroll
        for (int i = 0; i < 4; i++)
            wmma::load_matrix_sync(fa[i], As + (size_t)(wm * 64 + i * 16) * lda + kk, lda);
#pragma unroll
        for (int j = 0; j < 4; j++)
            wmma::load_matrix_sync(fb[j], Bg + (size_t)kk * ldB + j * 16, ldB);
#pragma unroll
        for (int i = 0; i < 4; i++)
#pragma unroll
            for (int j = 0; j < 4; j++)
                wmma::mma_sync(acc[i][j], fa[i], fb[j], acc[i][j]);
    }
}

// K=128 chunk; warp covers 64 rows x 32 cols
__device__ __forceinline__ void mma32h(const bf16* As64, int lda, const bf16* __restrict__ Bg,
                                       int ldB, FC acc[4][2])
{
#pragma unroll
    for (int kk = 0; kk < 128; kk += 16) {
        FA fa[4];
        FB fb[2];
#pragma unroll
        for (int i = 0; i < 4; i++)
            wmma::load_matrix_sync(fa[i], As64 + (size_t)(i * 16) * lda + kk, lda);
#pragma unroll
        for (int j = 0; j < 2; j++)
            wmma::load_matrix_sync(fb[j], Bg + (size_t)kk * ldB + j * 16, ldB);
#pragma unroll
        for (int i = 0; i < 4; i++)
#pragma unroll
            for (int j = 0; j < 2; j++)
                wmma::mma_sync(acc[i][j], fa[i], fb[j], acc[i][j]);
    }
}

__device__ __forceinline__ void zero_acc(FC acc[4][4]) {
#pragma unroll
    for (int i = 0; i < 4; i++)
#pragma unroll
        for (int j = 0; j < 4; j++) wmma::fill_fragment(acc[i][j], 0.f);
}
__device__ __forceinline__ void zero2(FC acc[4][2]) {
#pragma unroll
    for (int i = 0; i < 4; i++)
#pragma unroll
        for (int j = 0; j < 2; j++) wmma::fill_fragment(acc[i][j], 0.f);
}

__device__ __forceinline__ void dump_P(float* P, FC acc[4][4], int wm, int wn) {
#pragma unroll
    for (int i = 0; i < 4; i++)
#pragma unroll
        for (int j = 0; j < 4; j++)
            wmma::store_matrix_sync(P + (wm * 64 + i * 16) * PSTR + wn * 64 + j * 16,
                                    acc[i][j], PSTR, wmma::mem_row_major);
}

// dump 64x32 warp result into 64x132 P
__device__ __forceinline__ void dump32(float* P, FC acc[4][2], int w) {
#pragma unroll
    for (int i = 0; i < 4; i++)
#pragma unroll
        for (int j = 0; j < 2; j++)
            wmma::store_matrix_sync(P + (i * 16) * PSTR + w * 32 + j * 16,
                                    acc[i][j], PSTR, wmma::mem_row_major);
}

// shared: w1 (+SiLU) into hid region, via per-warp Dw (128-row kernels)
__device__ __forceinline__ void w1_to_hid(const bf16* As, bf16* hid, float* Dw,
                                          const bf16* __restrict__ W1T,
                                          int wm, int wn, int lane, FC acc[4][4])
{
    const int rloc = lane >> 1;
    const int h8 = (lane & 1) * 8;
#pragma unroll
    for (int t = 0; t < 2; t++) {
        zero_acc(acc);
        mma_loopS(As, TSA, W1T + t * 128 + wn * 64, 256, wm, acc);
#pragma unroll
        for (int i = 0; i < 4; i++) {
#pragma unroll
            for (int j = 0; j < 4; j++) {
                wmma::store_matrix_sync(Dw, acc[i][j], 20, wmma::mem_row_major);
                __syncwarp();
                int r = wm * 64 + i * 16 + rloc;
                int c = t * 128 + wn * 64 + j * 16 + h8;
#pragma unroll
                for (int c4 = 0; c4 < 2; c4++) {
                    float4 v = *(const float4*)(Dw + rloc * 20 + h8 + c4 * 4);
                    v.x = v.x / (1.f + __expf(-v.x));
                    v.y = v.y / (1.f + __expf(-v.y));
                    v.z = v.z / (1.f + __expf(-v.z));
                    v.w = v.w / (1.f + __expf(-v.w));
                    st_bf4(hid + (size_t)r * HSTR + c + c4 * 4, v);
                }
                __syncwarp();
            }
        }
    }
}

// shared: w2 + residual(from gmem fp32) -> out (128-row kernels)
__device__ __forceinline__ void w2_out(const bf16* hid, float* Dw,
                                       const bf16* __restrict__ W2T,
                                       const float* __restrict__ Rin, float* __restrict__ out,
                                       int rowBase, int M, int wm, int wn, int lane, FC acc[4][4])
{
    const int rloc = lane >> 1;
    const int h8 = (lane & 1) * 8;
    zero_acc(acc);
#pragma unroll
    for (int ch = 0; ch < 2; ch++)
        mma_loopS(hid + ch * 128, HSTR, W2T + (size_t)(ch * 128) * 128 + wn * 64, 128, wm, acc);
    __syncthreads();
#pragma unroll
    for (int i = 0; i < 4; i++) {
#pragma unroll
        for (int j = 0; j < 4; j++) {
            wmma::store_matrix_sync(Dw, acc[i][j], 20, wmma::mem_row_major);
            __syncwarp();
            int row = rowBase + wm * 64 + i * 16 + rloc;
            int c = wn * 64 + j * 16 + h8;
            if (row < M) {
#pragma unroll
                for (int c4 = 0; c4 < 2; c4++) {
                    float4 v = *(const float4*)(Dw + rloc * 20 + h8 + c4 * 4);
                    float4 rv = *(const float4*)(Rin + (size_t)row * 128 + c + c4 * 4);
                    v.x += rv.x; v.y += rv.y; v.z += rv.z; v.w += rv.w;
                    *(float4*)(out + (size_t)row * 128 + c + c4 * 4) = v;
                }
            }
            __syncwarp();
        }
    }
}

// per-warp epilogue through a 16x68 fp32 dump region (qkv)
__device__ __forceinline__ void epi_bias(float* Dw, FC acc[4][4],
                                         int wm, int wn, int lane, int rowBase,
                                         const float* bias, float* C, int M)
{
    const int rloc = lane >> 1;
    const int half = lane & 1;
#pragma unroll
    for (int i = 0; i < 4; i++) {
#pragma unroll
        for (int j = 0; j < 4; j++)
            wmma::store_matrix_sync(Dw + j * 16, acc[i][j], 68, wmma::mem_row_major);
        __syncwarp();
        int row = rowBase + wm * 64 + i * 16 + rloc;
        if (row < M) {
#pragma unroll
            for (int c4 = 0; c4 < 8; c4++) {
                int c = half * 32 + c4 * 4;
                float4 v = *(const float4*)(Dw + rloc * 68 + c);
                int gc = wn * 64 + c;
                float4 bv = *(const float4*)(bias + gc);
                v.x += bv.x; v.y += bv.y; v.z += bv.z; v.w += bv.w;
                *(float4*)(C + (size_t)row * 128 + gc) = v;
            }
        }
        __syncwarp();
    }
}

// ---------------- QKV fused ----------------
__global__ void __launch_bounds__(128) qkv15(
    const float* __restrict__ nf, const bf16* __restrict__ wT,
    const float* __restrict__ bq, const float* __restrict__ bk, const float* __restrict__ bv,
    const float* __restrict__ lnw, const float* __restrict__ lnb,
    float* __restrict__ Q, float* __restrict__ K, float* __restrict__ V)
{
    extern __shared__ char smraw[];
    bf16* As = (bf16*)smraw;
    float* Ds = (float*)(smraw + AS_BYTES);
    const int tid = threadIdx.x;
    const int w = tid >> 5, lane = tid & 31;
    const int wm = w >> 1, wn = w & 1;
    const int rowBase = blockIdx.x * 128;

    stage_ln(nf, lnw, lnb, As, rowBase, NN, w, lane);
    __syncthreads();

    const bf16* Wts[3] = {wT + OT_WQ, wT + OT_WK, wT + OT_WV};
    const float* bs[3] = {bq, bk, bv};
    float* outs[3] = {Q, K, V};

#pragma unroll
    for (int t = 0; t < 3; t++) {
        FC acc[4][4];
        zero_acc(acc);
        mma_loopS(As, TSA, Wts[t] + wn * 64, 128, wm, acc);
        epi_bias(Ds + w * DW_FLOATS, acc, wm, wn, lane, rowBase, bs[t], outs[t], NN);
    }
}

// ---------------- attnA64: 64-edge blocks, 4 blocks/SM ----------------
__global__ void __launch_bounds__(128, 4) attnA64(
    const float* __restrict__ ef,
    const bf16* __restrict__ WeT, const bf16* __restrict__ WoeT,
    const float* __restrict__ ln1w, const float* __restrict__ ln1b,
    const float* __restrict__ be, const float* __restrict__ boe,
    const float* __restrict__ Qm, const float* __restrict__ Km, const float* __restrict__ Vm,
    const int* __restrict__ src, const int* __restrict__ dst,
    float* __restrict__ emid, float* __restrict__ wV, float* __restrict__ z)
{
    extern __shared__ char smraw[];
    bf16* As = (bf16*)smraw;                     // 64 x TSA bf16
    float* P = (float*)(smraw + AS64_BYTES);     // 64 x 132 fp32
    const int tid = threadIdx.x;
    const int w = tid >> 5, lane = tid & 31;
    const int rowBase = blockIdx.x * 64;

    // 1) proj = LN1e(ef) @ We -> P
    stage_ln64(ef, ln1w, ln1b, As, rowBase, EE, w, lane);
    __syncthreads();

    FC acc[4][2];
    zero2(acc);
    mma32h(As, TSA, WeT + w * 32, 128, acc);
    __syncthreads();
    dump32(P, acc, w);
    __syncthreads();

    // 2) scoring: 2 threads per edge, 4 heads each; eo -> As (bf16)
    {
        const int r = tid >> 1;
        const int h0 = (tid & 1) * 4;
        const size_t e = (size_t)rowBase + r;
        const int sN = src[e], dN = dst[e];
        const float* Kp = Km + (size_t)sN * 128;
        const float* Qp = Qm + (size_t)dN * 128;
        const float* Vp = Vm + (size_t)sN * 128;
        float* wd = wV + (size_t)dN * 128;
#pragma unroll
        for (int h = h0; h < h0 + 4; h++) {
            const int c0 = h * 16;
            float sum = 0.f;
            float4 eo[4];
#pragma unroll
            for (int q4 = 0; q4 < 4; q4++) {
                float4 p = *(const float4*)(P + r * PSTR + c0 + q4 * 4);
                float4 bv = *(const float4*)(be + c0 + q4 * 4);
                p.x += bv.x; p.y += bv.y; p.z += bv.z; p.w += bv.w;
                float4 kk = *(const float4*)(Kp + c0 + q4 * 4);
                float4 qq = *(const float4*)(Qp + c0 + q4 * 4);
                float s0 = fminf(5.f, fmaxf(-5.f, kk.x * qq.x * 0.25f));
                float s1 = fminf(5.f, fmaxf(-5.f, kk.y * qq.y * 0.25f));
                float s2 = fminf(5.f, fmaxf(-5.f, kk.z * qq.z * 0.25f));
                float s3 = fminf(5.f, fmaxf(-5.f, kk.w * qq.w * 0.25f));
                eo[q4] = make_float4(s0 * p.x, s1 * p.y, s2 * p.z, s3 * p.w);
                sum += eo[q4].x + eo[q4].y + eo[q4].z + eo[q4].w;
            }
#pragma unroll
            for (int q4 = 0; q4 < 4; q4++)
                st_bf4(As + r * TSA + c0 + q4 * 4, eo[q4]);
            float wgt = __expf(fminf(5.f, fmaxf(-5.f, sum)));
#pragma unroll
            for (int q4 = 0; q4 < 4; q4++) {
                float4 vv = *(const float4*)(Vp + c0 + q4 * 4);
                red4(wd + c0 + q4 * 4, make_float4(vv.x * wgt, vv.y * wgt, vv.z * wgt, vv.w * wgt));
            }
            atomicAdd(z + (size_t)dN * 8 + h, wgt);
        }
    }
    __syncthreads();

    // 3) emid = eo @ Wo_e + bo_e + ef
    zero2(acc);
    mma32h(As, TSA, WoeT + w * 32, 128, acc);
    __syncthreads();
    dump32(P, acc, w);
    __syncthreads();
    {
        const int r = tid >> 1;
        const int hsel = tid & 1;
        const size_t row = (size_t)rowBase + r;
#pragma unroll
        for (int c4 = 0; c4 < 16; c4++) {
            int c = hsel * 64 + c4 * 4;
            float4 v = *(const float4*)(P + r * PSTR + c);
            float4 bb = *(const float4*)(boe + c);
            float4 rv = *(const float4*)(ef + row * 128 + c);
            v.x += bb.x + rv.x; v.y += bb.y + rv.y; v.z += bb.z + rv.z; v.w += bb.w + rv.w;
            *(float4*)(emid + row * 128 + c) = v;
        }
    }
}

// ---------------- mlpE64: 64-row blocks, 3 blocks/SM (round-13 proven) ----------------
__global__ void __launch_bounds__(128, 3) mlpE64(
    const float* __restrict__ emid,
    const bf16* __restrict__ W1T, const bf16* __restrict__ W2T,
    const float* __restrict__ ln2w, const float* __restrict__ ln2b,
    float* __restrict__ oute)
{
    extern __shared__ char smraw[];
    bf16* As = (bf16*)smraw;                              // 64 x TSA bf16
    bf16* hid = (bf16*)(smraw + AS64_BYTES);              // 64 x HSTR bf16
    float* Dw = (float*)(smraw + AS64_BYTES + H64BYTES) + (threadIdx.x >> 5) * DWS_FLOATS;
    const int tid = threadIdx.x;
    const int w = tid >> 5, lane = tid & 31;
    const int rloc = lane >> 1;
    const int h8 = (lane & 1) * 8;
    const int rowBase = blockIdx.x * 64;

    stage_ln64(emid, ln2w, ln2b, As, rowBase, EE, w, lane);
    __syncthreads();

    // w1: C = 64 x 256 ; warp w covers cols [w*64, w*64+64)
    {
        FC acc[4][4];
        zero_acc(acc);
#pragma unroll
        for (int kk = 0; kk < 128; kk += 16) {
            FA fa[4];
            FB fb[4];
#pragma unroll
            for (int i = 0; i < 4; i++)
                wmma::load_matrix_sync(fa[i], As + (size_t)(i * 16) * TSA + kk, TSA);
#pragma unroll
            for (int j = 0; j < 4; j++)
                wmma::load_matrix_sync(fb[j], W1T + (size_t)kk * 256 + w * 64 + j * 16, 256);
#pragma unroll
            for (int i = 0; i < 4; i++)
#pragma unroll
                for (int j = 0; j < 4; j++)
                    wmma::mma_sync(acc[i][j], fa[i], fb[j], acc[i][j]);
        }
#pragma unroll
        for (int i = 0; i < 4; i++) {
#pragma unroll
            for (int j = 0; j < 4; j++) {
                wmma::store_matrix_sync(Dw, acc[i][j], 20, wmma::mem_row_major);
                __syncwarp();
                int r = i * 16 + rloc;
                int c = w * 64 + j * 16 + h8;
#pragma unroll
                for (int c4 = 0; c4 < 2; c4++) {
                    float4 v = *(const float4*)(Dw + rloc * 20 + h8 + c4 * 4);
                    v.x = v.x / (1.f + __expf(-v.x));
                    v.y = v.y / (1.f + __expf(-v.y));
                    v.z = v.z / (1.f + __expf(-v.z));
                    v.w = v.w / (1.f + __expf(-v.w));
                    st_bf4(hid + (size_t)r * HSTR + c + c4 * 4, v);
                }
                __syncwarp();
            }
        }
    }
    __syncthreads();

    // w2: C = 64 x 128, K=256 ; warp w covers cols [w*32, w*32+32)
    {
        FC acc[4][2];
        zero2(acc);
#pragma unroll
        for (int ch = 0; ch < 2; ch++)
            mma32h(hid + ch * 128, HSTR, W2T + (size_t)(ch * 128) * 128 + w * 32, 128, acc);
        __syncthreads();
#pragma unroll
        for (int i = 0; i < 4; i++) {
#pragma unroll
            for (int j = 0; j < 2; j++) {
                wmma::store_matrix_sync(Dw, acc[i][j], 20, wmma::mem_row_major);
                __syncwarp();
                size_t row = (size_t)rowBase + i * 16 + rloc;
                int c = w * 32 + j * 16 + h8;
#pragma unroll
                for (int c4 = 0; c4 < 2; c4++) {
                    float4 v = *(const float4*)(Dw + rloc * 20 + h8 + c4 * 4);
                    float4 rv = *(const float4*)(emid + row * 128 + c + c4 * 4);
                    v.x += rv.x; v.y += rv.y; v.z += rv.z; v.w += rv.w;
                    *(float4*)(oute + row * 128 + c + c4 * 4) = v;
                }
                __syncwarp();
            }
        }
    }
}

// ---------------- nodeN ----------------
__global__ void __launch_bounds__(128) nodeN(
    const float* __restrict__ wV, const float* __restrict__ z,
    const float* __restrict__ nf,
    const bf16* __restrict__ WonT, const bf16* __restrict__ W1T, const bf16* __restrict__ W2T,
    const float* __restrict__ bon,
    const float* __restrict__ ln2w, const float* __restrict__ ln2b,
    float* __restrict__ hmid, float* __restrict__ outh)
{
    extern __shared__ char smraw[];
    bf16* As = (bf16*)smraw;
    float* P = (float*)(smraw + AS_BYTES);
    bf16* hid = (bf16*)P;
    float* Dw = (float*)(smraw + OFF_DW) + (threadIdx.x >> 5) * DWS_FLOATS;
    float2* MV = (float2*)(smraw + OFF_MV);
    const int tid = threadIdx.x;
    const int w = tid >> 5, lane = tid & 31;
    const int wm = w >> 1, wn = w & 1;
    const int rowBase = blockIdx.x * 128;

    stage_div(wV, z, As, rowBase, NN, tid);
    __syncthreads();
    FC acc[4][4];
    zero_acc(acc);
    mma_loopS(As, TSA, WonT + wn * 64, 128, wm, acc);
    __syncthreads();
    dump_P(P, acc, wm, wn);
    __syncthreads();
    {
        const int r = tid;
        const int row = rowBase + r;
        if (row < NN) {
            float s = 0.f, ss = 0.f;
#pragma unroll
            for (int c4 = 0; c4 < 32; c4++) {
                int c = c4 * 4;
                float4 v = *(const float4*)(P + r * PSTR + c);
                float4 bb = *(const float4*)(bon + c);
                float4 rv = *(const float4*)(nf + (size_t)row * 128 + c);
                v.x += bb.x + rv.x; v.y += bb.y + rv.y; v.z += bb.z + rv.z; v.w += bb.w + rv.w;
                *(float4*)(P + r * PSTR + c) = v;
                *(float4*)(hmid + (size_t)row * 128 + c) = v;
                s += v.x + v.y + v.z + v.w;
                ss += v.x * v.x + v.y * v.y + v.z * v.z + v.w * v.w;
            }
            float m = s * (1.f / 128.f);
            float var = ss * (1.f / 128.f) - m * m;
            MV[r] = make_float2(m, rsqrtf(var + 1e-5f));
        } else {
            MV[r] = make_float2(0.f, 0.f);
        }
    }
    __syncthreads();

    {
        float4 w4 = ((const float4*)ln2w)[lane];
        float4 b4 = ((const float4*)ln2b)[lane];
#pragma unroll
        for (int rr = 0; rr < 32; rr++) {
            int r = w * 32 + rr;
            float2 mv = MV[r];
            float4 v = *(const float4*)(P + r * PSTR + lane * 4);
            v.x = (v.x - mv.x) * mv.y * w4.x + b4.x;
            v.y = (v.y - mv.x) * mv.y * w4.y + b4.y;
            v.z = (v.z - mv.x) * mv.y * w4.z + b4.z;
            v.w = (v.w - mv.x) * mv.y * w4.w + b4.w;
            st_bf4(As + r * TSA + lane * 4, v);
        }
    }
    __syncthreads();

    w1_to_hid(As, hid, Dw, W1T, wm, wn, lane, acc);
    __syncthreads();
    w2_out(hid, Dw, W2T, hmid, outh, rowBase, NN, wm, wn, lane, acc);
}

// ---------------- weight prep ----------------
struct WPrep {
    const float* in[10];
    bf16* out[10];
    int n[10];
};
__global__ void wprep_all(WPrep wp)
{
    int t = blockIdx.y;
    int count = wp.n[t];
    const float* in = wp.in[t];
    bf16* out = wp.out[t];
    for (int idx = blockIdx.x * 256 + threadIdx.x; idx < count; idx += gridDim.x * 256)
        out[idx] = __float2bfloat16_rn(in[idx]);
}

// ---------------- launch ----------------
extern "C" void kernel_launch(void* const* d_in, const int* in_sizes, int n_in,
                              void* d_out, int out_size)
{
    const float* node_feats = (const float*)d_in[0];
    const float* edge_feats = (const float*)d_in[1];
    const int*   src        = (const int*)d_in[2];
    const int*   dst        = (const int*)d_in[3];
    const float* ln1n_w = (const float*)d_in[4];
    const float* ln1n_b = (const float*)d_in[5];
    const float* ln1e_w = (const float*)d_in[6];
    const float* ln1e_b = (const float*)d_in[7];
    const float* ln2n_w = (const float*)d_in[8];
    const float* ln2n_b = (const float*)d_in[9];
    const float* ln2e_w = (const float*)d_in[10];
    const float* ln2e_b = (const float*)d_in[11];
    const float* Wq = (const float*)d_in[12];
    const float* bq = (const float*)d_in[13];
    const float* Wk = (const float*)d_in[14];
    const float* bk = (const float*)d_in[15];
    const float* Wv = (const float*)d_in[16];
    const float* bv = (const float*)d_in[17];
    const float* We = (const float*)d_in[18];
    const float* be = (const float*)d_in[19];
    const float* Wo_n = (const float*)d_in[20];
    const float* bo_n = (const float*)d_in[21];
    const float* Wo_e = (const float*)d_in[22];
    const float* bo_e = (const float*)d_in[23];
    const float* mlp_n_w1 = (const float*)d_in[24];
    const float* mlp_n_w2 = (const float*)d_in[25];
    const float* mlp_e_w1 = (const float*)d_in[26];
    const float* mlp_e_w2 = (const float*)d_in[27];

    float* outh = (float*)d_out;
    float* oute = outh + (size_t)NN * DD;

    float *p_Q, *p_K, *p_V, *p_wV, *p_z, *p_hmid, *p_emid;
    bf16 *p_wB;
    cudaGetSymbolAddress((void**)&p_Q, g_Q);
    cudaGetSymbolAddress((void**)&p_K, g_K);
    cudaGetSymbolAddress((void**)&p_V, g_V);
    cudaGetSymbolAddress((void**)&p_wV, g_wV);
    cudaGetSymbolAddress((void**)&p_z, g_z);
    cudaGetSymbolAddress((void**)&p_hmid, g_hmid);
    cudaGetSymbolAddress((void**)&p_emid, g_emid);
    cudaGetSymbolAddress((void**)&p_wB, g_wB);

    static cudaStream_t sA = nullptr;
    static cudaEvent_t evF = nullptr, evJ = nullptr;
    if (!sA) {
        cudaStreamCreateWithFlags(&sA, cudaStreamNonBlocking);
        cudaEventCreateWithFlags(&evF, cudaEventDisableTiming);
        cudaEventCreateWithFlags(&evJ, cudaEventDisableTiming);
    }

    cudaFuncSetAttribute(qkv15, cudaFuncAttributeMaxDynamicSharedMemorySize, SMEM_G);
    cudaFuncSetAttribute(attnA64, cudaFuncAttributeMaxDynamicSharedMemorySize, SMEM_A64);
    cudaFuncSetAttribute(mlpE64, cudaFuncAttributeMaxDynamicSharedMemorySize, SMEM_M64);
    cudaFuncSetAttribute(nodeN, cudaFuncAttributeMaxDynamicSharedMemorySize, SMEM_N);

    cudaMemsetAsync(p_wV, 0, (size_t)NN * DD * sizeof(float));
    cudaMemsetAsync(p_z, 0, (size_t)NN * HH * sizeof(float));

    WPrep wp;
    wp.in[0] = Wq;       wp.out[0] = p_wB + OT_WQ;  wp.n[0] = 16384;
    wp.in[1] = Wk;       wp.out[1] = p_wB + OT_WK;  wp.n[1] = 16384;
    wp.in[2] = Wv;       wp.out[2] = p_wB + OT_WV;  wp.n[2] = 16384;
    wp.in[3] = Wo_n;     wp.out[3] = p_wB + OT_WON; wp.n[3] = 16384;
    wp.in[4] = Wo_e;     wp.out[4] = p_wB + OT_WOE; wp.n[4] = 16384;
    wp.in[5] = We;       wp.out[5] = p_wB + OT_WE;  wp.n[5] = 16384;
    wp.in[6] = mlp_n_w1; wp.out[6] = p_wB + OT_W1N; wp.n[6] = 32768;
    wp.in[7] = mlp_n_w2; wp.out[7] = p_wB + OT_W2N; wp.n[7] = 32768;
    wp.in[8] = mlp_e_w1; wp.out[8] = p_wB + OT_W1E; wp.n[8] = 32768;
    wp.in[9] = mlp_e_w2; wp.out[9] = p_wB + OT_W2E; wp.n[9] = 32768;
    wprep_all<<<dim3(32, 10), 256>>>(wp);

    const int gN = (NN + 127) / 128;   // 391
    const int gE64 = EE / 64;          // 12500

    qkv15<<<gN, 128, SMEM_G>>>(node_feats, p_wB, bq, bk, bv, ln1n_w, ln1n_b, p_Q, p_K, p_V);

    attnA64<<<gE64, 128, SMEM_A64>>>(edge_feats, p_wB + OT_WE, p_wB + OT_WOE,
                                     ln1e_w, ln1e_b, be, bo_e,
                                     p_Q, p_K, p_V, src, dst,
                                     p_emid, p_wV, p_z);

    // fork: edge MLP on side stream, node chain on main stream
    cudaEventRecord(evF, 0);
    cudaStreamWaitEvent(sA, evF, 0);

    mlpE64<<<gE64, 128, SMEM_M64, sA>>>(p_emid, p_wB + OT_W1E, p_wB + OT_W2E,
                                        ln2e_w, ln2e_b, oute);

    nodeN<<<gN, 128, SMEM_N>>>(p_wV, p_z, node_feats,
                               p_wB + OT_WON, p_wB + OT_W1N, p_wB + OT_W2N,
                               bo_n, ln2n_w, ln2n_b, p_hmid, outh);

    // join
    cudaEventRecord(evJ, sA);
    cudaStreamWaitEvent(0, evJ, 0);
}

// round 16
// speedup vs baseline: 1.1027x; 1.0744x over previous
#include <cuda_runtime.h>
#include <cuda_bf16.h>
#include <mma.h>
#include <math.h>
#include <cstdint>

using namespace nvcuda;
typedef __nv_bfloat16 bf16;
typedef __nv_bfloat162 bf162;
typedef unsigned int u32;

#define NN 50000
#define EE 800000
#define DD 128
#define HH 8

// ---------------- scratch ----------------
__device__ float g_Q[(size_t)NN * DD];
__device__ float g_K[(size_t)NN * DD];
__device__ float g_V[(size_t)NN * DD];
__device__ float g_wV[(size_t)NN * DD];
__device__ float g_z[(size_t)NN * HH];
__device__ float g_hmid[(size_t)NN * DD];
__device__ float g_emid[(size_t)EE * DD];
__device__ bf16  g_wB[229376];  // bf16 weights, natural [K,N]

#define OT_WQ   0
#define OT_WK   16384
#define OT_WV   32768
#define OT_WON  49152
#define OT_WOE  65536
#define OT_WE   81920
#define OT_W1N  98304
#define OT_W2N  131072
#define OT_W1E  163840
#define OT_W2E  196608

#define TSA 136                         // bf16 stride for A tile
#define AS_BYTES (128 * TSA * 2)        // 34816
#define AS64_BYTES (64 * TSA * 2)       // 17408
#define DW_FLOATS (16 * 68)             // per-warp fp32 dump (qkv kernel)
#define SMEM_G (AS_BYTES + 4 * DW_FLOATS * 4)     // 52224

#define PSTR 132
#define PBYTES (128 * PSTR * 4)         // 67584
#define P64BYTES (64 * PSTR * 4)        // 33792
#define HSTR 264                        // bf16 hid stride
#define H64BYTES (64 * HSTR * 2)        // 33792
#define DWS_FLOATS (16 * 20)            // per-warp small dump

#define SMEM_A64 (AS64_BYTES + P64BYTES)               // attnA64: 51200 (4 blocks/SM)
#define SMEM_M64 (AS64_BYTES + H64BYTES + 4 * DWS_FLOATS * 4)  // mlpE64: 56320 (4 blocks/SM)
#define OFF_DW  (AS_BYTES + PBYTES)
#define OFF_MV  (OFF_DW + 4 * DWS_FLOATS * 4)
#define SMEM_N  (OFF_MV + 128 * 8)                     // nodeN: 108544

typedef wmma::fragment<wmma::matrix_a, 16, 16, 16, bf16, wmma::row_major> FA;
typedef wmma::fragment<wmma::matrix_b, 16, 16, 16, bf16, wmma::row_major> FB;
typedef wmma::fragment<wmma::accumulator, 16, 16, 16, float> FC;

__device__ __forceinline__ void st_bf4(bf16* p, float4 v) {
    *(bf162*)(p)     = __floats2bfloat162_rn(v.x, v.y);
    *(bf162*)(p + 2) = __floats2bfloat162_rn(v.z, v.w);
}
__device__ __forceinline__ void red4(float* p, float4 v) {
    asm volatile("red.global.add.v4.f32 [%0], {%1,%2,%3,%4};"
                 :: "l"(p), "f"(v.x), "f"(v.y), "f"(v.z), "f"(v.w) : "memory");
}

// ---- staging: 128 rows, 4 warps ----
__device__ __forceinline__ void stage_ln(const float* __restrict__ A,
                                         const float* __restrict__ lnw,
                                         const float* __restrict__ lnb,
                                         bf16* As, int rowBase, int M, int w, int lane)
{
    float4 w4 = ((const float4*)lnw)[lane];
    float4 b4 = ((const float4*)lnb)[lane];
#pragma unroll
    for (int rr = 0; rr < 32; rr++) {
        int r = w * 32 + rr;
        int row = rowBase + r;
        float4 v = make_float4(0.f, 0.f, 0.f, 0.f);
        if (row < M) {
            v = *(const float4*)(A + (size_t)row * 128 + lane * 4);
            float s = v.x + v.y + v.z + v.w;
            float ss = v.x * v.x + v.y * v.y + v.z * v.z + v.w * v.w;
#pragma unroll
            for (int o = 16; o > 0; o >>= 1) {
                s += __shfl_xor_sync(0xffffffffu, s, o);
                ss += __shfl_xor_sync(0xffffffffu, ss, o);
            }
            float m = s * (1.f / 128.f);
            float var = ss * (1.f / 128.f) - m * m;
            float rs = rsqrtf(var + 1e-5f);
            v.x = (v.x - m) * rs * w4.x + b4.x;
            v.y = (v.y - m) * rs * w4.y + b4.y;
            v.z = (v.z - m) * rs * w4.z + b4.z;
            v.w = (v.w - m) * rs * w4.w + b4.w;
        }
        st_bf4(As + r * TSA + lane * 4, v);
    }
}

// ---- staging: 64 rows, 4 warps (16 rows each) ----
__device__ __forceinline__ void stage_ln64(const float* __restrict__ A,
                                           const float* __restrict__ lnw,
                                           const float* __restrict__ lnb,
                                           bf16* As, int rowBase, int M, int w, int lane)
{
    float4 w4 = ((const float4*)lnw)[lane];
    float4 b4 = ((const float4*)lnb)[lane];
#pragma unroll
    for (int rr = 0; rr < 16; rr++) {
        int r = w * 16 + rr;
        int row = rowBase + r;
        float4 v = make_float4(0.f, 0.f, 0.f, 0.f);
        if (row < M) {
            v = *(const float4*)(A + (size_t)row * 128 + lane * 4);
            float s = v.x + v.y + v.z + v.w;
            float ss = v.x * v.x + v.y * v.y + v.z * v.z + v.w * v.w;
#pragma unroll
            for (int o = 16; o > 0; o >>= 1) {
                s += __shfl_xor_sync(0xffffffffu, s, o);
                ss += __shfl_xor_sync(0xffffffffu, ss, o);
            }
            float m = s * (1.f / 128.f);
            float var = ss * (1.f / 128.f) - m * m;
            float rs = rsqrtf(var + 1e-5f);
            v.x = (v.x - m) * rs * w4.x + b4.x;
            v.y = (v.y - m) * rs * w4.y + b4.y;
            v.z = (v.z - m) * rs * w4.z + b4.z;
            v.w = (v.w - m) * rs * w4.w + b4.w;
        }
        st_bf4(As + r * TSA + lane * 4, v);
    }
}

// staging with wV/z division
__device__ __forceinline__ void stage_div(const float* __restrict__ wV,
                                          const float* __restrict__ z,
                                          bf16* As, int rowBase, int M, int tid)
{
#pragma unroll
    for (int it = 0; it < 32; it++) {
        int f = tid + it * 128;
        int r = f >> 5;
        int c = (f & 31) << 2;
        int row = rowBase + r;
        float4 v = make_float4(0.f, 0.f, 0.f, 0.f);
        if (row < M) {
            v = *(const float4*)(wV + (size_t)row * 128 + c);
            float inv = 1.f / (z[(size_t)row * 8 + (c >> 4)] + 1e-8f);
            v.x *= inv; v.y *= inv; v.z *= inv; v.w *= inv;
        }
        st_bf4(As + r * TSA + c, v);
    }
}

// one K=128 chunk; warp tile 64x64 (4 warps: wm=w>>1, wn=w&1)
__device__ __forceinline__ void mma_loopS(const bf16* As, int lda, const bf16* __restrict__ Bg,
                                          int ldB, int wm, FC acc[4][4])
{
#pragma unroll
    for (int kk = 0; kk < 128; kk += 16) {
        FA fa[4];
        FB fb[4];
#pragma unroll
        for (int i = 0; i < 4; i++)
            wmma::load_matrix_sync(fa[i], As + (size_t)(wm * 64 + i * 16) * lda + kk, lda);
#pragma unroll
        for (int j = 0; j < 4; j++)
            wmma::load_matrix_sync(fb[j], Bg + (size_t)kk * ldB + j * 16, ldB);
#pragma unroll
        for (int i = 0; i < 4; i++)
#pragma unroll
            for (int j = 0; j < 4; j++)
                wmma::mma_sync(acc[i][j], fa[i], fb[j], acc[i][j]);
    }
}

// K=128 chunk; warp covers 64 rows x 32 cols
__device__ __forceinline__ void mma32h(const bf16* As64, int lda, const bf16* __restrict__ Bg,
                                       int ldB, FC acc[4][2])
{
#pragma unroll
    for (int kk = 0; kk < 128; kk += 16) {
        FA fa[4];
        FB fb[2];
#pragma unroll
        for (int i = 0; i < 4; i++)
            wmma::load_matrix_sync(fa[i], As64 + (size_t)(i * 16) * lda + kk, lda);
#pragma unroll
        for (int j = 0; j < 2; j++)
            wmma::load_matrix_sync(fb[j], Bg + (size_t)kk * ldB + j * 16, ldB);
#pragma unroll
        for (int i = 0; i < 4; i++)
#pragma unroll
            for (int j = 0; j < 2; j++)
                wmma::mma_sync(acc[i][j], fa[i], fb[j], acc[i][j]);
    }
}

__device__ __forceinline__ void zero_acc(FC acc[4][4]) {
#pragma unroll
    for (int i = 0; i < 4; i++)
#pragma unroll
        for (int j = 0; j < 4; j++) wmma::fill_fragment(acc[i][j], 0.f);
}
__device__ __forceinline__ void zero2(FC acc[4][2]) {
#pragma unroll
    for (int i = 0; i < 4; i++)
#pragma unroll
        for (int j = 0; j < 2; j++) wmma::fill_fragment(acc[i][j], 0.f);
}

__device__ __forceinline__ void dump_P(float* P, FC acc[4][4], int wm, int wn) {
#pragma unroll
    for (int i = 0; i < 4; i++)
#pragma unroll
        for (int j = 0; j < 4; j++)
            wmma::store_matrix_sync(P + (wm * 64 + i * 16) * PSTR + wn * 64 + j * 16,
                                    acc[i][j], PSTR, wmma::mem_row_major);
}

// dump 64x32 warp result into 64x132 P
__device__ __forceinline__ void dump32(float* P, FC acc[4][2], int w) {
#pragma unroll
    for (int i = 0; i < 4; i++)
#pragma unroll
        for (int j = 0; j < 2; j++)
            wmma::store_matrix_sync(P + (i * 16) * PSTR + w * 32 + j * 16,
                                    acc[i][j], PSTR, wmma::mem_row_major);
}

// shared: w1 (+SiLU) into hid region, via per-warp Dw (128-row kernels)
__device__ __forceinline__ void w1_to_hid(const bf16* As, bf16* hid, float* Dw,
                                          const bf16* __restrict__ W1T,
                                          int wm, int wn, int lane, FC acc[4][4])
{
    const int rloc = lane >> 1;
    const int h8 = (lane & 1) * 8;
#pragma unroll
    for (int t = 0; t < 2; t++) {
        zero_acc(acc);
        mma_loopS(As, TSA, W1T + t * 128 + wn * 64, 256, wm, acc);
#pragma unroll
        for (int i = 0; i < 4; i++) {
#pragma unroll
            for (int j = 0; j < 4; j++) {
                wmma::store_matrix_sync(Dw, acc[i][j], 20, wmma::mem_row_major);
                __syncwarp();
                int r = wm * 64 + i * 16 + rloc;
                int c = t * 128 + wn * 64 + j * 16 + h8;
#pragma unroll
                for (int c4 = 0; c4 < 2; c4++) {
                    float4 v = *(const float4*)(Dw + rloc * 20 + h8 + c4 * 4);
                    v.x = v.x / (1.f + __expf(-v.x));
                    v.y = v.y / (1.f + __expf(-v.y));
                    v.z = v.z / (1.f + __expf(-v.z));
                    v.w = v.w / (1.f + __expf(-v.w));
                    st_bf4(hid + (size_t)r * HSTR + c + c4 * 4, v);
                }
                __syncwarp();
            }
        }
    }
}

// shared: w2 + residual(from gmem fp32) -> out (128-row kernels)
__device__ __forceinline__ void w2_out(const bf16* hid, float* Dw,
                                       const bf16* __restrict__ W2T,
                                       const float* __restrict__ Rin, float* __restrict__ out,
                                       int rowBase, int M, int wm, int wn, int lane, FC acc[4][4])
{
    const int rloc = lane >> 1;
    const int h8 = (lane & 1) * 8;
    zero_acc(acc);
#pragma unroll
    for (int ch = 0; ch < 2; ch++)
        mma_loopS(hid + ch * 128, HSTR, W2T + (size_t)(ch * 128) * 128 + wn * 64, 128, wm, acc);
    __syncthreads();
#pragma unroll
    for (int i = 0; i < 4; i++) {
#pragma unroll
        for (int j = 0; j < 4; j++) {
            wmma::store_matrix_sync(Dw, acc[i][j], 20, wmma::mem_row_major);
            __syncwarp();
            int row = rowBase + wm * 64 + i * 16 + rloc;
            int c = wn * 64 + j * 16 + h8;
            if (row < M) {
#pragma unroll
                for (int c4 = 0; c4 < 2; c4++) {
                    float4 v = *(const float4*)(Dw + rloc * 20 + h8 + c4 * 4);
                    float4 rv = *(const float4*)(Rin + (size_t)row * 128 + c + c4 * 4);
                    v.x += rv.x; v.y += rv.y; v.z += rv.z; v.w += rv.w;
                    *(float4*)(out + (size_t)row * 128 + c + c4 * 4) = v;
                }
            }
            __syncwarp();
        }
    }
}

// per-warp epilogue through a 16x68 fp32 dump region (qkv)
__device__ __forceinline__ void epi_bias(float* Dw, FC acc[4][4],
                                         int wm, int wn, int lane, int rowBase,
                                         const float* bias, float* C, int M)
{
    const int rloc = lane >> 1;
    const int half = lane & 1;
#pragma unroll
    for (int i = 0; i < 4; i++) {
#pragma unroll
        for (int j = 0; j < 4; j++)
            wmma::store_matrix_sync(Dw + j * 16, acc[i][j], 68, wmma::mem_row_major);
        __syncwarp();
        int row = rowBase + wm * 64 + i * 16 + rloc;
        if (row < M) {
#pragma unroll
            for (int c4 = 0; c4 < 8; c4++) {
                int c = half * 32 + c4 * 4;
                float4 v = *(const float4*)(Dw + rloc * 68 + c);
                int gc = wn * 64 + c;
                float4 bv = *(const float4*)(bias + gc);
                v.x += bv.x; v.y += bv.y; v.z += bv.z; v.w += bv.w;
                *(float4*)(C + (size_t)row * 128 + gc) = v;
            }
        }
        __syncwarp();
    }
}

// ---------------- QKV fused ----------------
__global__ void __launch_bounds__(128) qkv16(
    const float* __restrict__ nf, const bf16* __restrict__ wT,
    const float* __restrict__ bq, const float* __restrict__ bk, const float* __restrict__ bv,
    const float* __restrict__ lnw, const float* __restrict__ lnb,
    float* __restrict__ Q, float* __restrict__ K, float* __restrict__ V)
{
    extern __shared__ char smraw[];
    bf16* As = (bf16*)smraw;
    float* Ds = (float*)(smraw + AS_BYTES);
    const int tid = threadIdx.x;
    const int w = tid >> 5, lane = tid & 31;
    const int wm = w >> 1, wn = w & 1;
    const int rowBase = blockIdx.x * 128;

    stage_ln(nf, lnw, lnb, As, rowBase, NN, w, lane);
    __syncthreads();

    const bf16* Wts[3] = {wT + OT_WQ, wT + OT_WK, wT + OT_WV};
    const float* bs[3] = {bq, bk, bv};
    float* outs[3] = {Q, K, V};

#pragma unroll
    for (int t = 0; t < 3; t++) {
        FC acc[4][4];
        zero_acc(acc);
        mma_loopS(As, TSA, Wts[t] + wn * 64, 128, wm, acc);
        epi_bias(Ds + w * DW_FLOATS, acc, wm, wn, lane, rowBase, bs[t], outs[t], NN);
    }
}

// ---------------- attnA64: 64-edge blocks, 4 blocks/SM ----------------
__global__ void __launch_bounds__(128, 4) attnA64(
    const float* __restrict__ ef,
    const bf16* __restrict__ WeT, const bf16* __restrict__ WoeT,
    const float* __restrict__ ln1w, const float* __restrict__ ln1b,
    const float* __restrict__ be, const float* __restrict__ boe,
    const float* __restrict__ Qm, const float* __restrict__ Km, const float* __restrict__ Vm,
    const int* __restrict__ src, const int* __restrict__ dst,
    float* __restrict__ emid, float* __restrict__ wV, float* __restrict__ z)
{
    extern __shared__ char smraw[];
    bf16* As = (bf16*)smraw;                     // 64 x TSA bf16
    float* P = (float*)(smraw + AS64_BYTES);     // 64 x 132 fp32
    const int tid = threadIdx.x;
    const int w = tid >> 5, lane = tid & 31;
    const int rowBase = blockIdx.x * 64;

    // 1) proj = LN1e(ef) @ We -> P
    stage_ln64(ef, ln1w, ln1b, As, rowBase, EE, w, lane);
    __syncthreads();

    FC acc[4][2];
    zero2(acc);
    mma32h(As, TSA, WeT + w * 32, 128, acc);
    __syncthreads();
    dump32(P, acc, w);
    __syncthreads();

    // 2) scoring: 2 threads per edge, 4 heads each; eo -> As (bf16)
    {
        const int r = tid >> 1;
        const int h0 = (tid & 1) * 4;
        const size_t e = (size_t)rowBase + r;
        const int sN = src[e], dN = dst[e];
        const float* Kp = Km + (size_t)sN * 128;
        const float* Qp = Qm + (size_t)dN * 128;
        const float* Vp = Vm + (size_t)sN * 128;
        float* wd = wV + (size_t)dN * 128;
        float zacc[4];
#pragma unroll
        for (int hh = 0; hh < 4; hh++) {
            const int h = h0 + hh;
            const int c0 = h * 16;
            float sum = 0.f;
            float4 eo[4];
#pragma unroll
            for (int q4 = 0; q4 < 4; q4++) {
                float4 p = *(const float4*)(P + r * PSTR + c0 + q4 * 4);
                float4 bv = *(const float4*)(be + c0 + q4 * 4);
                p.x += bv.x; p.y += bv.y; p.z += bv.z; p.w += bv.w;
                float4 kk = *(const float4*)(Kp + c0 + q4 * 4);
                float4 qq = *(const float4*)(Qp + c0 + q4 * 4);
                float s0 = fminf(5.f, fmaxf(-5.f, kk.x * qq.x * 0.25f));
                float s1 = fminf(5.f, fmaxf(-5.f, kk.y * qq.y * 0.25f));
                float s2 = fminf(5.f, fmaxf(-5.f, kk.z * qq.z * 0.25f));
                float s3 = fminf(5.f, fmaxf(-5.f, kk.w * qq.w * 0.25f));
                eo[q4] = make_float4(s0 * p.x, s1 * p.y, s2 * p.z, s3 * p.w);
                sum += eo[q4].x + eo[q4].y + eo[q4].z + eo[q4].w;
            }
#pragma unroll
            for (int q4 = 0; q4 < 4; q4++)
                st_bf4(As + r * TSA + c0 + q4 * 4, eo[q4]);
            float wgt = __expf(fminf(5.f, fmaxf(-5.f, sum)));
            zacc[hh] = wgt;
#pragma unroll
            for (int q4 = 0; q4 < 4; q4++) {
                float4 vv = *(const float4*)(Vp + c0 + q4 * 4);
                red4(wd + c0 + q4 * 4, make_float4(vv.x * wgt, vv.y * wgt, vv.z * wgt, vv.w * wgt));
            }
        }
        red4(z + (size_t)dN * 8 + h0, make_float4(zacc[0], zacc[1], zacc[2], zacc[3]));
    }
    __syncthreads();

    // 3) emid = eo @ Wo_e + bo_e + ef
    zero2(acc);
    mma32h(As, TSA, WoeT + w * 32, 128, acc);
    __syncthreads();
    dump32(P, acc, w);
    __syncthreads();
    {
        const int r = tid >> 1;
        const int hsel = tid & 1;
        const size_t row = (size_t)rowBase + r;
#pragma unroll
        for (int c4 = 0; c4 < 16; c4++) {
            int c = hsel * 64 + c4 * 4;
            float4 v = *(const float4*)(P + r * PSTR + c);
            float4 bb = *(const float4*)(boe + c);
            float4 rv = *(const float4*)(ef + row * 128 + c);
            v.x += bb.x + rv.x; v.y += bb.y + rv.y; v.z += bb.z + rv.z; v.w += bb.w + rv.w;
            *(float4*)(emid + row * 128 + c) = v;
        }
    }
}

// ---------------- mlpE64: 64-row blocks, low-reg w1, 4 blocks/SM ----------------
__global__ void __launch_bounds__(128, 4) mlpE64(
    const float* __restrict__ emid,
    const bf16* __restrict__ W1T, const bf16* __restrict__ W2T,
    const float* __restrict__ ln2w, const float* __restrict__ ln2b,
    float* __restrict__ oute)
{
    extern __shared__ char smraw[];
    bf16* As = (bf16*)smraw;                              // 64 x TSA bf16
    bf16* hid = (bf16*)(smraw + AS64_BYTES);              // 64 x HSTR bf16
    float* Dw = (float*)(smraw + AS64_BYTES + H64BYTES) + (threadIdx.x >> 5) * DWS_FLOATS;
    const int tid = threadIdx.x;
    const int w = tid >> 5, lane = tid & 31;
    const int rloc = lane >> 1;
    const int h8 = (lane & 1) * 8;
    const int rowBase = blockIdx.x * 64;

    stage_ln64(emid, ln2w, ln2b, As, rowBase, EE, w, lane);
    __syncthreads();

    // w1: C = 64 x 256 ; warp w covers cols [w*64, w*64+64) in two 32-col passes
#pragma unroll
    for (int pp = 0; pp < 2; pp++) {
        FC acc[4][2];
        zero2(acc);
        mma32h(As, TSA, W1T + w * 64 + pp * 32, 256, acc);
#pragma unroll
        for (int i = 0; i < 4; i++) {
#pragma unroll
            for (int j = 0; j < 2; j++) {
                wmma::store_matrix_sync(Dw, acc[i][j], 20, wmma::mem_row_major);
                __syncwarp();
                int r = i * 16 + rloc;
                int c = w * 64 + pp * 32 + j * 16 + h8;
#pragma unroll
                for (int c4 = 0; c4 < 2; c4++) {
                    float4 v = *(const float4*)(Dw + rloc * 20 + h8 + c4 * 4);
                    v.x = v.x / (1.f + __expf(-v.x));
                    v.y = v.y / (1.f + __expf(-v.y));
                    v.z = v.z / (1.f + __expf(-v.z));
                    v.w = v.w / (1.f + __expf(-v.w));
                    st_bf4(hid + (size_t)r * HSTR + c + c4 * 4, v);
                }
                __syncwarp();
            }
        }
    }
    __syncthreads();

    // w2: C = 64 x 128, K=256 ; warp w covers cols [w*32, w*32+32)
    {
        FC acc[4][2];
        zero2(acc);
#pragma unroll
        for (int ch = 0; ch < 2; ch++)
            mma32h(hid + ch * 128, HSTR, W2T + (size_t)(ch * 128) * 128 + w * 32, 128, acc);
        __syncthreads();
#pragma unroll
        for (int i = 0; i < 4; i++) {
#pragma unroll
            for (int j = 0; j < 2; j++) {
                wmma::store_matrix_sync(Dw, acc[i][j], 20, wmma::mem_row_major);
                __syncwarp();
                size_t row = (size_t)rowBase + i * 16 + rloc;
                int c = w * 32 + j * 16 + h8;
#pragma unroll
                for (int c4 = 0; c4 < 2; c4++) {
                    float4 v = *(const float4*)(Dw + rloc * 20 + h8 + c4 * 4);
                    float4 rv = *(const float4*)(emid + row * 128 + c + c4 * 4);
                    v.x += rv.x; v.y += rv.y; v.z += rv.z; v.w += rv.w;
                    *(float4*)(oute + row * 128 + c + c4 * 4) = v;
                }
                __syncwarp();
            }
        }
    }
}

// ---------------- nodeN ----------------
__global__ void __launch_bounds__(128) nodeN(
    const float* __restrict__ wV, const float* __restrict__ z,
    const float* __restrict__ nf,
    const bf16* __restrict__ WonT, const bf16* __restrict__ W1T, const bf16* __restrict__ W2T,
    const float* __restrict__ bon,
    const float* __restrict__ ln2w, const float* __restrict__ ln2b,
    float* __restrict__ hmid, float* __restrict__ outh)
{
    extern __shared__ char smraw[];
    bf16* As = (bf16*)smraw;
    float* P = (float*)(smraw + AS_BYTES);
    bf16* hid = (bf16*)P;
    float* Dw = (float*)(smraw + OFF_DW) + (threadIdx.x >> 5) * DWS_FLOATS;
    float2* MV = (float2*)(smraw + OFF_MV);
    const int tid = threadIdx.x;
    const int w = tid >> 5, lane = tid & 31;
    const int wm = w >> 1, wn = w & 1;
    const int rowBase = blockIdx.x * 128;

    stage_div(wV, z, As, rowBase, NN, tid);
    __syncthreads();
    FC acc[4][4];
    zero_acc(acc);
    mma_loopS(As, TSA, WonT + wn * 64, 128, wm, acc);
    __syncthreads();
    dump_P(P, acc, wm, wn);
    __syncthreads();
    {
        const int r = tid;
        const int row = rowBase + r;
        if (row < NN) {
            float s = 0.f, ss = 0.f;
#pragma unroll
            for (int c4 = 0; c4 < 32; c4++) {
                int c = c4 * 4;
                float4 v = *(const float4*)(P + r * PSTR + c);
                float4 bb = *(const float4*)(bon + c);
                float4 rv = *(const float4*)(nf + (size_t)row * 128 + c);
                v.x += bb.x + rv.x; v.y += bb.y + rv.y; v.z += bb.z + rv.z; v.w += bb.w + rv.w;
                *(float4*)(P + r * PSTR + c) = v;
                *(float4*)(hmid + (size_t)row * 128 + c) = v;
                s += v.x + v.y + v.z + v.w;
                ss += v.x * v.x + v.y * v.y + v.z * v.z + v.w * v.w;
            }
            float m = s * (1.f / 128.f);
            float var = ss * (1.f / 128.f) - m * m;
            MV[r] = make_float2(m, rsqrtf(var + 1e-5f));
        } else {
            MV[r] = make_float2(0.f, 0.f);
        }
    }
    __syncthreads();

    {
        float4 w4 = ((const float4*)ln2w)[lane];
        float4 b4 = ((const float4*)ln2b)[lane];
#pragma unroll
        for (int rr = 0; rr < 32; rr++) {
            int r = w * 32 + rr;
            float2 mv = MV[r];
            float4 v = *(const float4*)(P + r * PSTR + lane * 4);
            v.x = (v.x - mv.x) * mv.y * w4.x + b4.x;
            v.y = (v.y - mv.x) * mv.y * w4.y + b4.y;
            v.z = (v.z - mv.x) * mv.y * w4.z + b4.z;
            v.w = (v.w - mv.x) * mv.y * w4.w + b4.w;
            st_bf4(As + r * TSA + lane * 4, v);
        }
    }
    __syncthreads();

    w1_to_hid(As, hid, Dw, W1T, wm, wn, lane, acc);
    __syncthreads();
    w2_out(hid, Dw, W2T, hmid, outh, rowBase, NN, wm, wn, lane, acc);
}

// ---------------- weight prep ----------------
struct WPrep {
    const float* in[10];
    bf16* out[10];
    int n[10];
};
__global__ void wprep_all(WPrep wp)
{
    int t = blockIdx.y;
    int count = wp.n[t];
    const float* in = wp.in[t];
    bf16* out = wp.out[t];
    for (int idx = blockIdx.x * 256 + threadIdx.x; idx < count; idx += gridDim.x * 256)
        out[idx] = __float2bfloat16_rn(in[idx]);
}

// ---------------- launch ----------------
extern "C" void kernel_launch(void* const* d_in, const int* in_sizes, int n_in,
                              void* d_out, int out_size)
{
    const float* node_feats = (const float*)d_in[0];
    const float* edge_feats = (const float*)d_in[1];
    const int*   src        = (const int*)d_in[2];
    const int*   dst        = (const int*)d_in[3];
    const float* ln1n_w = (const float*)d_in[4];
    const float* ln1n_b = (const float*)d_in[5];
    const float* ln1e_w = (const float*)d_in[6];
    const float* ln1e_b = (const float*)d_in[7];
    const float* ln2n_w = (const float*)d_in[8];
    const float* ln2n_b = (const float*)d_in[9];
    const float* ln2e_w = (const float*)d_in[10];
    const float* ln2e_b = (const float*)d_in[11];
    const float* Wq = (const float*)d_in[12];
    const float* bq = (const float*)d_in[13];
    const float* Wk = (const float*)d_in[14];
    const float* bk = (const float*)d_in[15];
    const float* Wv = (const float*)d_in[16];
    const float* bv = (const float*)d_in[17];
    const float* We = (const float*)d_in[18];
    const float* be = (const float*)d_in[19];
    const float* Wo_n = (const float*)d_in[20];
    const float* bo_n = (const float*)d_in[21];
    const float* Wo_e = (const float*)d_in[22];
    const float* bo_e = (const float*)d_in[23];
    const float* mlp_n_w1 = (const float*)d_in[24];
    const float* mlp_n_w2 = (const float*)d_in[25];
    const float* mlp_e_w1 = (const float*)d_in[26];
    const float* mlp_e_w2 = (const float*)d_in[27];

    float* outh = (float*)d_out;
    float* oute = outh + (size_t)NN * DD;

    float *p_Q, *p_K, *p_V, *p_wV, *p_z, *p_hmid, *p_emid;
    bf16 *p_wB;
    cudaGetSymbolAddress((void**)&p_Q, g_Q);
    cudaGetSymbolAddress((void**)&p_K, g_K);
    cudaGetSymbolAddress((void**)&p_V, g_V);
    cudaGetSymbolAddress((void**)&p_wV, g_wV);
    cudaGetSymbolAddress((void**)&p_z, g_z);
    cudaGetSymbolAddress((void**)&p_hmid, g_hmid);
    cudaGetSymbolAddress((void**)&p_emid, g_emid);
    cudaGetSymbolAddress((void**)&p_wB, g_wB);

    static cudaStream_t sA = nullptr;
    static cudaEvent_t evF = nullptr, evJ = nullptr;
    if (!sA) {
        cudaStreamCreateWithFlags(&sA, cudaStreamNonBlocking);
        cudaEventCreateWithFlags(&evF, cudaEventDisableTiming);
        cudaEventCreateWithFlags(&evJ, cudaEventDisableTiming);
    }

    cudaFuncSetAttribute(qkv16, cudaFuncAttributeMaxDynamicSharedMemorySize, SMEM_G);
    cudaFuncSetAttribute(attnA64, cudaFuncAttributeMaxDynamicSharedMemorySize, SMEM_A64);
    cudaFuncSetAttribute(mlpE64, cudaFuncAttributeMaxDynamicSharedMemorySize, SMEM_M64);
    cudaFuncSetAttribute(nodeN, cudaFuncAttributeMaxDynamicSharedMemorySize, SMEM_N);

    cudaMemsetAsync(p_wV, 0, (size_t)NN * DD * sizeof(float));
    cudaMemsetAsync(p_z, 0, (size_t)NN * HH * sizeof(float));

    WPrep wp;
    wp.in[0] = Wq;       wp.out[0] = p_wB + OT_WQ;  wp.n[0] = 16384;
    wp.in[1] = Wk;       wp.out[1] = p_wB + OT_WK;  wp.n[1] = 16384;
    wp.in[2] = Wv;       wp.out[2] = p_wB + OT_WV;  wp.n[2] = 16384;
    wp.in[3] = Wo_n;     wp.out[3] = p_wB + OT_WON; wp.n[3] = 16384;
    wp.in[4] = Wo_e;     wp.out[4] = p_wB + OT_WOE; wp.n[4] = 16384;
    wp.in[5] = We;       wp.out[5] = p_wB + OT_WE;  wp.n[5] = 16384;
    wp.in[6] = mlp_n_w1; wp.out[6] = p_wB + OT_W1N; wp.n[6] = 32768;
    wp.in[7] = mlp_n_w2; wp.out[7] = p_wB + OT_W2N; wp.n[7] = 32768;
    wp.in[8] = mlp_e_w1; wp.out[8] = p_wB + OT_W1E; wp.n[8] = 32768;
    wp.in[9] = mlp_e_w2; wp.out[9] = p_wB + OT_W2E; wp.n[9] = 32768;
    wprep_all<<<dim3(32, 10), 256>>>(wp);

    const int gN = (NN + 127) / 128;   // 391
    const int gE64 = EE / 64;          // 12500

    qkv16<<<gN, 128, SMEM_G>>>(node_feats, p_wB, bq, bk, bv, ln1n_w, ln1n_b, p_Q, p_K, p_V);

    attnA64<<<gE64, 128, SMEM_A64>>>(edge_feats, p_wB + OT_WE, p_wB + OT_WOE,
                                     ln1e_w, ln1e_b, be, bo_e,
                                     p_Q, p_K, p_V, src, dst,
                                     p_emid, p_wV, p_z);

    // fork: edge MLP on side stream, node chain on main stream
    cudaEventRecord(evF, 0);
    cudaStreamWaitEvent(sA, evF, 0);

    mlpE64<<<gE64, 128, SMEM_M64, sA>>>(p_emid, p_wB + OT_W1E, p_wB + OT_W2E,
                                        ln2e_w, ln2e_b, oute);

    nodeN<<<gN, 128, SMEM_N>>>(p_wV, p_z, node_feats,
                               p_wB + OT_WON, p_wB + OT_W1N, p_wB + OT_W2N,
                               bo_n, ln2n_w, ln2n_b, p_hmid, outh);

    // join
    cudaEventRecord(evJ, sA);
    cudaStreamWaitEvent(0, evJ, 0);
}